// round 12
// baseline (speedup 1.0000x reference)
#include <cuda_runtime.h>
#include <cuda_bf16.h>
#include <cstdint>
#include <cstddef>

typedef __nv_bfloat16 bf16;
#define NTOK 2048
#define HEADS 8
#define STAGES 3

// ---------------- scratch (static device globals) ----------------
__device__ float g_qkv_cls[(size_t)NTOK * 3072];
__device__ float g_qk_reg [(size_t)NTOK * 2048];
__device__ bf16  g_Xc[(size_t)NTOK * 2048];
__device__ bf16  g_Xr[(size_t)NTOK * 2048];
__device__ bf16  g_Wc[(size_t)3072 * 2048];
__device__ bf16  g_Wr[(size_t)2048 * 2048];
__device__ bf16  g_qc[(size_t)HEADS * NTOK * 256];
__device__ bf16  g_kc[(size_t)HEADS * NTOK * 256];
__device__ bf16  g_qr[(size_t)HEADS * NTOK * 256];
__device__ bf16  g_kr[(size_t)HEADS * NTOK * 256];
__device__ bf16  g_vn[(size_t)NTOK * 2048];             // [n][h*128+d], lo at +1024
__device__ bf16  g_Vt[(size_t)HEADS * 128 * 4096];
__device__ float g_Scls[(size_t)HEADS * NTOK * NTOK];   // scores; later reused for PV partials
__device__ float g_Sreg[(size_t)HEADS * NTOK * NTOK];
__device__ float g_Svv [(size_t)NTOK * NTOK];           // SUM over heads of vn.vn^T (symmetric)
__device__ bf16  g_P[(size_t)HEADS * NTOK * 4096];

// ---------------- helpers ----------------
__device__ __forceinline__ uint32_t s2u(const void* p) {
    uint32_t a;
    asm("{ .reg .u64 t; cvta.to.shared.u64 t, %1; cvt.u32.u64 %0, t; }" : "=r"(a) : "l"(p));
    return a;
}
#define SWZ(x) ((x) ^ (((x) >> 3) & 0x70))

__device__ __forceinline__ void cpasync16(uint32_t s, const void* g) {
    asm volatile("cp.async.cg.shared.global [%0], [%1], 16;" :: "r"(s), "l"(g) : "memory");
}
#define CP_COMMIT() asm volatile("cp.async.commit_group;" ::: "memory")
#define CP_WAIT(n)  asm volatile("cp.async.wait_group %0;" :: "n"(n) : "memory")

__device__ __forceinline__ void ldsm4(uint32_t& r0, uint32_t& r1, uint32_t& r2, uint32_t& r3, uint32_t a) {
    asm volatile("ldmatrix.sync.aligned.m8n8.x4.shared.b16 {%0,%1,%2,%3}, [%4];"
                 : "=r"(r0), "=r"(r1), "=r"(r2), "=r"(r3) : "r"(a));
}
__device__ __forceinline__ void mma16816(float* d, const uint32_t* a, uint32_t b0, uint32_t b1) {
    asm volatile(
        "mma.sync.aligned.m16n8k16.row.col.f32.bf16.bf16.f32 "
        "{%0,%1,%2,%3}, {%4,%5,%6,%7}, {%8,%9}, {%0,%1,%2,%3};"
        : "+f"(d[0]), "+f"(d[1]), "+f"(d[2]), "+f"(d[3])
        : "r"(a[0]), "r"(a[1]), "r"(a[2]), "r"(a[3]), "r"(b0), "r"(b1));
}

// ---------------- HMMA NT GEMM, per-mode tiles, flat grids ----------------
// Warp layout (both MW): 2 m-groups x 4 n-groups (wm = wid&1, wn = wid>>1).
//   MW=1 (64x128):  MT=2 -> 2 A-ldsm + 2 B-ldsm per k16 (minimum for 8 mma)
//   MW=2 (128x128): MT=4 -> 4 A-ldsm + 2 B-ldsm per k16 (minimum for 16 mma)
// MODE 1: PV split-K  MW=1, 3 CTA/SM, grid 768:  z=x>>5 (head*3+seg), yt=x&31
// MODE 2: qkv merged  MW=1, 3 CTA/SM, grid 1280: x<768 cls tile (writes x_ori for
//                     v-columns j>=2048), else reg tile
// MODE 3: scores+vv   MW=2, 2 CTA/SM, grid 4232: x<136 vv symm tile FIRST
template<int MODE>
__global__ __launch_bounds__(256, (MODE == 3) ? 2 : 3) void hm_gemm_k(float* __restrict__ xout)
{
    extern __shared__ char dsm[];
    constexpr int MW = (MODE == 3) ? 2 : 1;
    constexpr int MT = 2 * MW;                     // m16 tiles per warp
    constexpr int MROWS = MW * 64;
    constexpr uint32_t ABYTES = (uint32_t)MROWS * 128u;
    constexpr uint32_t STGB = ABYTES + 16384u;
    const size_t QH = (size_t)NTOK * 256, SH = (size_t)NTOK * NTOK;

    const bf16 *A, *B; float* C;
    int lda, ldb, ldc, K, i0, j0;
    bool symm = false; int bi = 0, bj = 0;
    bool singleseg = false, vcols = false;

    if (MODE == 2) {
        K = 1024; lda = 2048; ldb = 2048;
        const int t = blockIdx.x;
        if (t < 768) {
            A = g_Xc; B = g_Wc; C = g_qkv_cls; ldc = 3072;
            i0 = (t / 24) * 64;  j0 = (t % 24) * 128;
            vcols = (j0 >= 2048);
        } else {
            const int t2 = t - 768;
            A = g_Xr; B = g_Wr; C = g_qk_reg; ldc = 2048;
            i0 = (t2 >> 4) * 64;  j0 = (t2 & 15) * 128;
        }
    } else if (MODE == 3) {
        const int x = blockIdx.x;
        if (x < 136) {                 // vv long tiles first (LPT scheduling)
            symm = true;
            bi = (int)((33.0f - sqrtf(fmaxf(0.0f, 1089.0f - 8.0f * (float)x))) * 0.5f);
            while ((bi + 1) * (33 - (bi + 1)) / 2 <= x) bi++;
            while (bi * (33 - bi) / 2 > x) bi--;
            bj = bi + (x - bi * (33 - bi) / 2);
            i0 = bi * 128; j0 = bj * 128;
            A = g_vn; B = g_vn; C = g_Svv; lda = 2048; ldb = 2048; ldc = 2048; K = 1024;
        } else {
            const int t = x - 136;
            const int z = t >> 8, r = t & 255;
            K = 128; lda = 256; ldb = 256; ldc = 2048;
            if (z < 8) { A = g_qc + z * QH;       B = g_kc + z * QH;       C = g_Scls + z * SH; }
            else       { A = g_qr + (z - 8) * QH; B = g_kr + (z - 8) * QH; C = g_Sreg + (z - 8) * SH; }
            i0 = (r >> 4) * 128;  j0 = (r & 15) * 128;
        }
    } else {  // MODE 1: PV
        singleseg = true;
        const int z = blockIdx.x >> 5, yt = blockIdx.x & 31;
        const int head = z / 3, seg = z % 3;
        K = 2048;
        A = g_P  + (size_t)head * NTOK * 4096 + ((seg == 1) ? (size_t)K : 0);
        B = g_Vt + (size_t)head * 128  * 4096 + ((seg == 2) ? (size_t)K : 0);
        C = g_Scls + (size_t)z * NTOK * 128;
        lda = 4096; ldb = 4096; ldc = 128;
        i0 = yt * 64; j0 = 0;
    }

    const int nkc = K >> 6;
    const int NC  = singleseg ? nkc : 3 * nkc;
    const int tid = threadIdx.x;
    const uint32_t stage0 = (s2u(dsm) + 1023u) & ~1023u;

    const int lane = tid & 31, wid = tid >> 5;
    const int wm = wid & 1, wn = wid >> 1;         // 2 m-groups x 4 n-groups
    const int lt = lane >> 3, lr = lane & 7;
    const int arow = wm * (MT * 16) + (lt & 1) * 8 + lr;   // + mt*16
    const int brow = wn * 32 + (lt & 1) * 8 + lr;          // + np*16
    const int kbsub = (lt >> 1) * 16;
    const uint32_t xm = (uint32_t)(lr << 4);

    float acc[MT][4][4];
#pragma unroll
    for (int i = 0; i < MT; i++)
#pragma unroll
        for (int j = 0; j < 4; j++)
#pragma unroll
            for (int q = 0; q < 4; q++) acc[i][j][q] = 0.0f;

    auto fill = [&](int s, int c) {
        const bf16 *Ab, *Bb;
        if (MODE == 1) {
            const int kk = c << 6;
            Ab = A + kk;  Bb = B + kk;
        } else {
            const int seg = c / nkc, kk = (c - seg * nkc) << 6;
            Ab = A + ((seg == 1) ? K : 0) + kk;
            Bb = B + ((seg == 2) ? K : 0) + kk;
        }
        const uint32_t sA = stage0 + (uint32_t)s * STGB, sB = sA + ABYTES;
#pragma unroll
        for (int i = 0; i < 2 * MW; i++) {
            const int id = (i << 8) + tid;
            const int row = id >> 3, c16 = id & 7;
            const uint32_t so = SWZ((uint32_t)((row << 7) + (c16 << 4)));
            cpasync16(sA + so, Ab + (size_t)(i0 + row) * lda + (c16 << 3));
        }
#pragma unroll
        for (int i = 0; i < 4; i++) {
            const int id = (i << 8) + tid;
            const int row = id >> 3, c16 = id & 7;
            const uint32_t so = SWZ((uint32_t)((row << 7) + (c16 << 4)));
            cpasync16(sB + so, Bb + (size_t)(j0 + row) * ldb + (c16 << 3));
        }
    };

#pragma unroll
    for (int c = 0; c < STAGES; c++) { fill(c, c); CP_COMMIT(); }

    for (int c = 0; c < NC; ++c) {
        const int s = c - (c / STAGES) * STAGES;
        CP_WAIT(1);
        __syncthreads();
        if (c >= 1) {
            const int cn = c + 2;
            if (cn < NC) fill(cn - (cn / STAGES) * STAGES, cn);
            CP_COMMIT();
        }
        const uint32_t sA = stage0 + (uint32_t)s * STGB, sB = sA + ABYTES;
#pragma unroll
        for (int ks = 0; ks < 4; ks++) {
            const uint32_t koff = ((uint32_t)(ks * 32 + kbsub)) ^ xm;
            uint32_t a[MT][4], b[2][4];
#pragma unroll
            for (int mt = 0; mt < MT; mt++)
                ldsm4(a[mt][0], a[mt][1], a[mt][2], a[mt][3],
                      sA + (uint32_t)((arow + mt * 16) << 7) + koff);
#pragma unroll
            for (int np = 0; np < 2; np++)
                ldsm4(b[np][0], b[np][1], b[np][2], b[np][3],
                      sB + (uint32_t)((brow + np * 16) << 7) + koff);
#pragma unroll
            for (int mt = 0; mt < MT; mt++)
#pragma unroll
                for (int nt = 0; nt < 4; nt++)
                    mma16816(acc[mt][nt], a[mt], b[nt >> 1][nt & 1], b[nt >> 1][(nt & 1) + 2]);
        }
    }

    const int rq = lane >> 2, cq = (lane & 3) * 2;
#pragma unroll
    for (int mt = 0; mt < MT; mt++) {
        const int row = i0 + wm * (MT * 16) + mt * 16 + rq;
#pragma unroll
        for (int nt = 0; nt < 4; nt++) {
            const int col = j0 + wn * 32 + nt * 8 + cq;
            const float2 v0 = make_float2(acc[mt][nt][0], acc[mt][nt][1]);
            const float2 v1 = make_float2(acc[mt][nt][2], acc[mt][nt][3]);
            *(float2*)(C + (size_t)row * ldc + col)       = v0;
            *(float2*)(C + (size_t)(row + 8) * ldc + col) = v1;
            if (MODE == 2 && vcols) {   // x_ori: out[:,1024:2048] = v-block of qkv_cls
                *(float2*)(xout + (size_t)row * 2048 + col - 1024)       = v0;
                *(float2*)(xout + (size_t)(row + 8) * 2048 + col - 1024) = v1;
            }
        }
    }

    // mirror off-diagonal vv tile via padded smem transpose (MODE 3 only, MW=2)
    if (MODE == 3) {
        if (symm && bi != bj) {
            float* smf = (float*)dsm;              // 128 x 133 fp32 = 68KB < DS2
            __syncthreads();
#pragma unroll
            for (int mt = 0; mt < MT; mt++) {
                const int r = wm * (MT * 16) + mt * 16 + rq;
#pragma unroll
                for (int nt = 0; nt < 4; nt++) {
                    const int cc = wn * 32 + nt * 8 + cq;
                    smf[r * 133 + cc]           = acc[mt][nt][0];
                    smf[r * 133 + cc + 1]       = acc[mt][nt][1];
                    smf[(r + 8) * 133 + cc]     = acc[mt][nt][2];
                    smf[(r + 8) * 133 + cc + 1] = acc[mt][nt][3];
                }
            }
            __syncthreads();
            const int r2 = tid & 127;
            const int c2b = (tid >> 7) * 64;
            float* Crow = C + (size_t)(j0 + r2) * ldc + i0 + c2b;
#pragma unroll
            for (int q = 0; q < 16; q++) {
                float4 v = make_float4(smf[(c2b + 4 * q + 0) * 133 + r2],
                                       smf[(c2b + 4 * q + 1) * 133 + r2],
                                       smf[(c2b + 4 * q + 2) * 133 + r2],
                                       smf[(c2b + 4 * q + 3) * 133 + r2]);
                *(float4*)(Crow + 4 * q) = v;
            }
        }
    }
}

// ---------------- PV split-K reduce (x_ori now written by qkv epilogue) ----------------
__global__ __launch_bounds__(256) void pv_finish(const float* __restrict__ part, float* __restrict__ out)
{
    const size_t t = (size_t)blockIdx.x * 256 + threadIdx.x;   // over 2048*1024/4
    const size_t e = t * 4;
    const int n = (int)(e >> 10), c = (int)(e & 1023);
    const int h = c >> 7, d = c & 127;
    const size_t base = (((size_t)h * 3 * NTOK) + n) * 128 + d;
    const size_t sg = (size_t)NTOK * 128;
    float4 v0 = *(const float4*)(part + base);
    float4 v1 = *(const float4*)(part + base + sg);
    float4 v2 = *(const float4*)(part + base + 2 * sg);
    *(float4*)(out + (size_t)n * 2048 + c) =
        make_float4(v0.x + v1.x + v2.x, v0.y + v1.y + v2.y,
                    v0.z + v1.z + v2.z, v0.w + v1.w + v2.w);
}

// ---------------- merged prep: split x_cls/x_reg + transpose/split W_cls/W_reg --------
__device__ __forceinline__ void tsplit_body(
    const float* __restrict__ in, bf16* __restrict__ out,
    int R, int ldin, int ldout, int r0, int c0)
{
    __shared__ float t[32][33];
    const int tx = threadIdx.x & 31, ty = threadIdx.x >> 5;
#pragma unroll
    for (int i = 0; i < 4; i++)
        t[ty + i * 8][tx] = in[(size_t)(r0 + ty + i * 8) * ldin + c0 + tx];
    __syncthreads();
#pragma unroll
    for (int i = 0; i < 4; i++) {
        const int cc = ty + i * 8;
        const float v = t[tx][cc];
        const bf16 h = __float2bfloat16(v);
        out[(size_t)(c0 + cc) * ldout + r0 + tx]     = h;
        out[(size_t)(c0 + cc) * ldout + R + r0 + tx] = __float2bfloat16(v - __bfloat162float(h));
    }
}

__global__ __launch_bounds__(256) void prep(
    const float* __restrict__ xc, const float* __restrict__ xr,
    const float* __restrict__ Wcls, const float* __restrict__ Wreg)
{
    const int x = blockIdx.x;
    if (x < 16384) {                       // split x: 2 x 2048x1024 elements
        const size_t idx = (size_t)x * 256 + threadIdx.x;
        const int z = (idx >= (size_t)2048 * 1024);
        const size_t i = idx - (size_t)z * 2048 * 1024;
        const int n = (int)(i >> 10), c = (int)(i & 1023);
        const float v = (z == 0 ? xc : xr)[i];
        bf16* o = (z == 0 ? g_Xc : g_Xr) + (size_t)n * 2048 + c;
        const bf16 h = __float2bfloat16(v);
        o[0] = h;  o[1024] = __float2bfloat16(v - __bfloat162float(h));
    } else if (x < 16384 + 3072) {         // W_cls transpose+split: 96 x 32 tiles
        const int t2 = x - 16384;
        tsplit_body(Wcls, g_Wc, 1024, 3072, 2048, (t2 / 96) * 32, (t2 % 96) * 32);
    } else {                               // W_reg transpose+split: 64 x 32 tiles
        const int t2 = x - 16384 - 3072;
        tsplit_body(Wreg, g_Wr, 1024, 3072, 2048, (t2 / 64) * 32, (t2 % 64) * 32);
    }
}

// ---------------- transpose + split (generic, for Vt) ----------------
__global__ __launch_bounds__(256) void transpose_split(
    const float* __restrict__ in, bf16* __restrict__ out,
    int R, int ldin, int ldout, size_t zin, size_t zout)
{
    in  += (size_t)blockIdx.z * zin;
    out += (size_t)blockIdx.z * zout;
    tsplit_body(in, out, R, ldin, ldout, blockIdx.y * 32, blockIdx.x * 32);
}

// ---------------- L2-normalize + split ----------------
__global__ __launch_bounds__(256) void normalize_k()
{
    const int gid  = blockIdx.x * 8 + (threadIdx.x >> 5);
    const int lane = threadIdx.x & 31;
    const int op  = gid / (NTOK * HEADS);
    const int rem = gid - op * (NTOK * HEADS);
    const int n = rem >> 3, h = rem & 7;

    const float* src; bf16* dst; int lo_off;
    if (op == 0)      { src = g_qkv_cls + (size_t)n * 3072 + h * 128;        dst = g_qc + ((size_t)h * NTOK + n) * 256; lo_off = 128; }
    else if (op == 1) { src = g_qkv_cls + (size_t)n * 3072 + 1024 + h * 128; dst = g_kc + ((size_t)h * NTOK + n) * 256; lo_off = 128; }
    else if (op == 2) { src = g_qk_reg  + (size_t)n * 2048 + h * 128;        dst = g_qr + ((size_t)h * NTOK + n) * 256; lo_off = 128; }
    else if (op == 3) { src = g_qk_reg  + (size_t)n * 2048 + 1024 + h * 128; dst = g_kr + ((size_t)h * NTOK + n) * 256; lo_off = 128; }
    else              { src = g_qkv_cls + (size_t)n * 3072 + 2048 + h * 128; dst = g_vn + (size_t)n * 2048 + h * 128;   lo_off = 1024; }

    float4 v = *(const float4*)(src + lane * 4);
    float ss = v.x * v.x + v.y * v.y + v.z * v.z + v.w * v.w;
#pragma unroll
    for (int o = 16; o; o >>= 1) ss += __shfl_xor_sync(0xffffffffu, ss, o);
    const float r = 1.0f / sqrtf(ss);
    float a[4] = { v.x * r, v.y * r, v.z * r, v.w * r };
#pragma unroll
    for (int j = 0; j < 4; j++) {
        const bf16 h2 = __float2bfloat16(a[j]);
        dst[lane * 4 + j]          = h2;
        dst[lo_off + lane * 4 + j] = __float2bfloat16(a[j] - __bfloat162float(h2));
    }
}

// ---------------- FMA-only exp + block reductions ----------------
__device__ __forceinline__ float fast_exp(float x)
{
    float t = x * 1.4426950408889634f;
    t = fmaxf(t, -120.0f);
    float r = t + 12582912.0f;
    float f = t - (r - 12582912.0f);
    int   k = __float_as_int(r) - 0x4B400000;
    float p = 1.5403530393381609e-4f;
    p = fmaf(p, f, 1.3333558146428443e-3f);
    p = fmaf(p, f, 9.618129107628477e-3f);
    p = fmaf(p, f, 5.550410866482158e-2f);
    p = fmaf(p, f, 2.402265069591007e-1f);
    p = fmaf(p, f, 6.931471805599453e-1f);
    p = fmaf(p, f, 1.0f);
    return p * __int_as_float((k + 127) << 23);
}
__device__ __forceinline__ float block_max(float v, float* red)
{
#pragma unroll
    for (int o = 16; o; o >>= 1) v = fmaxf(v, __shfl_xor_sync(0xffffffffu, v, o));
    if ((threadIdx.x & 31) == 0) red[threadIdx.x >> 5] = v;
    __syncthreads();
    float r = red[0];
#pragma unroll
    for (int i = 1; i < 8; i++) r = fmaxf(r, red[i]);
    __syncthreads();
    return r;
}
__device__ __forceinline__ float block_sum(float v, float* red)
{
#pragma unroll
    for (int o = 16; o; o >>= 1) v += __shfl_xor_sync(0xffffffffu, v, o);
    if ((threadIdx.x & 31) == 0) red[threadIdx.x >> 5] = v;
    __syncthreads();
    float r = red[0];
#pragma unroll
    for (int i = 1; i < 8; i++) r += red[i];
    __syncthreads();
    return r;
}
// joint (a,b) block sum with a single barrier
__device__ __forceinline__ void block_sum2(float& a, float& b, float* red2)
{
#pragma unroll
    for (int o = 16; o; o >>= 1) {
        a += __shfl_xor_sync(0xffffffffu, a, o);
        b += __shfl_xor_sync(0xffffffffu, b, o);
    }
    if ((threadIdx.x & 31) == 0) {
        red2[(threadIdx.x >> 5) * 2]     = a;
        red2[(threadIdx.x >> 5) * 2 + 1] = b;
    }
    __syncthreads();
    float ra = red2[0], rb = red2[1];
#pragma unroll
    for (int i = 1; i < 8; i++) { ra += red2[i * 2]; rb += red2[i * 2 + 1]; }
    __syncthreads();
    a = ra; b = rb;
}

// ---------------- fused masked dual softmax + combine + sim_round2 -----------------
__global__ __launch_bounds__(256) void row_fuse(
    const float* __restrict__ cls_score, const float* __restrict__ fg_score,
    float* __restrict__ out_sim)
{
    const int n = blockIdx.x;
    const int tid = threadIdx.x;
    const int m0 = tid * 8;
    __shared__ float s_sc[NTOK];
    __shared__ float red[16];

    float fc[8], fr[8];
    float lsc = -1e30f, lfs = -1e30f;
#pragma unroll
    for (int j = 0; j < 8; j++) {
        const int m = m0 + j;
        const float a = cls_score[m], b = fg_score[m];
        fc[j] = a;  fr[j] = b;
        s_sc[m] = a;
        lsc = fmaxf(lsc, a);  lfs = fmaxf(lfs, b);
    }
    __syncthreads();
    const float Mc = 25.0f * block_max(lsc, red) + 1.0f;
    const float Mr = 25.0f * block_max(lfs, red) + 1.0f;
    const float cthr = s_sc[n] - 0.1f;
    const float fthr = fg_score[n] - 0.1f;
#pragma unroll
    for (int j = 0; j < 8; j++) {
        fc[j] = (fc[j] > cthr) ? 25.0f * fc[j] : 0.0f;
        fr[j] = (fr[j] > fthr) ? 25.0f * fr[j] : 0.0f;
    }

    float vvacc[8];
    {
        float4 v0 = *(const float4*)(g_Svv + (size_t)n * NTOK + m0);
        float4 v1 = *(const float4*)(g_Svv + (size_t)n * NTOK + m0 + 4);
        vvacc[0] = v0.x; vvacc[1] = v0.y; vvacc[2] = v0.z; vvacc[3] = v0.w;
        vvacc[4] = v1.x; vvacc[5] = v1.y; vvacc[6] = v1.z; vvacc[7] = v1.w;
    }

    float simacc[8];
#pragma unroll
    for (int j = 0; j < 8; j++) simacc[j] = 0.0f;

    for (int h = 0; h < HEADS; h++) {
        const size_t base = ((size_t)h * NTOK + n) * NTOK + m0;
        bf16* Pb = g_P + ((size_t)h * NTOK + n) * 4096 + m0;
        float ec[8], er[8];

        float4 s0 = *(const float4*)(g_Scls + base);
        float4 s1 = *(const float4*)(g_Scls + base + 4);
        ec[0] = fast_exp(s0.x * fc[0] - Mc);  ec[1] = fast_exp(s0.y * fc[1] - Mc);
        ec[2] = fast_exp(s0.z * fc[2] - Mc);  ec[3] = fast_exp(s0.w * fc[3] - Mc);
        ec[4] = fast_exp(s1.x * fc[4] - Mc);  ec[5] = fast_exp(s1.y * fc[5] - Mc);
        ec[6] = fast_exp(s1.z * fc[6] - Mc);  ec[7] = fast_exp(s1.w * fc[7] - Mc);
        float smc = ec[0] + ec[1] + ec[2] + ec[3] + ec[4] + ec[5] + ec[6] + ec[7];

        float4 r0 = *(const float4*)(g_Sreg + base);
        float4 r1 = *(const float4*)(g_Sreg + base + 4);
        er[0] = fast_exp(r0.x * fr[0] - Mr);  er[1] = fast_exp(r0.y * fr[1] - Mr);
        er[2] = fast_exp(r0.z * fr[2] - Mr);  er[3] = fast_exp(r0.w * fr[3] - Mr);
        er[4] = fast_exp(r1.x * fr[4] - Mr);  er[5] = fast_exp(r1.y * fr[5] - Mr);
        er[6] = fast_exp(r1.z * fr[6] - Mr);  er[7] = fast_exp(r1.w * fr[7] - Mr);
        float smr = er[0] + er[1] + er[2] + er[3] + er[4] + er[5] + er[6] + er[7];

        block_sum2(smc, smr, red);             // one barrier for both sums
        const float ic = 0.5f / smc, ir = 0.5f / smr;

        float pv[8];
#pragma unroll
        for (int j = 0; j < 8; j++) pv[j] = ec[j] * ic + er[j] * ir;

        union { __nv_bfloat162 h2[4]; uint4 u; } ph, pl;
#pragma unroll
        for (int j = 0; j < 4; j++) {
            const bf16 h0 = __float2bfloat16(pv[2 * j]);
            const bf16 h1 = __float2bfloat16(pv[2 * j + 1]);
            ph.h2[j] = __nv_bfloat162(h0, h1);
            pl.h2[j] = __nv_bfloat162(
                __float2bfloat16(pv[2 * j]     - __bfloat162float(h0)),
                __float2bfloat16(pv[2 * j + 1] - __bfloat162float(h1)));
        }
        *(uint4*)(Pb)        = ph.u;
        *(uint4*)(Pb + 2048) = pl.u;

#pragma unroll
        for (int j = 0; j < 8; j++) simacc[j] += pv[j];
    }

    float sm = 0.0f;
#pragma unroll
    for (int j = 0; j < 8; j++) { simacc[j] = fast_exp(simacc[j] * 0.125f - 1.0f); sm += simacc[j]; }
    sm = block_sum(sm, red);
    float msum = 0.0f;
#pragma unroll
    for (int j = 0; j < 8; j++) {
        const float soft = simacc[j] / sm;
        const float keep = (vvacc[j] > 6.0f) ? soft : 0.0f;
        simacc[j] = keep; msum += keep;
    }
    msum = block_sum(msum, red);
    const float rn = 1.0f / msum;
    float4 o0 = make_float4(simacc[0] * rn, simacc[1] * rn, simacc[2] * rn, simacc[3] * rn);
    float4 o1 = make_float4(simacc[4] * rn, simacc[5] * rn, simacc[6] * rn, simacc[7] * rn);
    *(float4*)(out_sim + (size_t)n * NTOK + m0)     = o0;
    *(float4*)(out_sim + (size_t)n * NTOK + m0 + 4) = o1;
}

// -------------------------------- launch ----------------------------------------
extern "C" void kernel_launch(void* const* d_in, const int* in_sizes, int n_in,
                              void* d_out, int out_size)
{
    (void)in_sizes; (void)n_in; (void)out_size;
    const float* x_cls     = (const float*)d_in[0];
    const float* x_reg     = (const float*)d_in[1];
    const float* cls_score = (const float*)d_in[2];
    const float* fg_score  = (const float*)d_in[3];
    const float* W_cls     = (const float*)d_in[4];
    const float* W_reg     = (const float*)d_in[5];
    float* out = (float*)d_out;

    float *qkv_cls, *Scls;
    bf16 *Vt;
    cudaGetSymbolAddress((void**)&qkv_cls, g_qkv_cls);
    cudaGetSymbolAddress((void**)&Vt, g_Vt);
    cudaGetSymbolAddress((void**)&Scls, g_Scls);

    const int DS1 = STAGES * 24576 + 1024;   // MW=1 stages (64x128), 3 CTAs/SM
    const int DS2 = STAGES * 32768 + 1024;   // MW=2 stages (128x128), 2 CTAs/SM
    cudaFuncSetAttribute((const void*)hm_gemm_k<1>, cudaFuncAttributeMaxDynamicSharedMemorySize, DS1);
    cudaFuncSetAttribute((const void*)hm_gemm_k<2>, cudaFuncAttributeMaxDynamicSharedMemorySize, DS1);
    cudaFuncSetAttribute((const void*)hm_gemm_k<3>, cudaFuncAttributeMaxDynamicSharedMemorySize, DS2);

    // 1) merged prep: split x_cls/x_reg + transpose/split W_cls/W_reg
    prep<<<16384 + 3072 + 2048, 256>>>(x_cls, x_reg, W_cls, W_reg);

    // 2) qkv projections (also writes x_ori -> out[:,1024:2048] from v-columns)
    hm_gemm_k<2><<<1280, 256, DS1>>>(out);

    // 3) normalize q/k/v; transpose v -> Vt split
    normalize_k<<<5 * NTOK * HEADS / 8, 256>>>();
    transpose_split<<<dim3(4, 64, 8), 256>>>(qkv_cls + 2048, Vt, 2048, 3072, 4096,
                                             128, (size_t)128 * 4096);

    // 4) scores (16 planes) + symmetric vv, 128x128 tiles @ 2 CTA/SM, vv LPT-first
    hm_gemm_k<3><<<4232, 256, DS2>>>(nullptr);

    // 5) fused softmax + sim (reads S*, writes P bf16 hi|lo + sim output)
    row_fuse<<<NTOK, 256>>>(cls_score, fg_score, out + (size_t)NTOK * NTOK);

    // 6) x = P @ V split-K partials (reuse g_Scls), then reduce -> out[:,0:1024]
    hm_gemm_k<1><<<768, 256, DS1>>>(nullptr);
    pv_finish<<<(NTOK * 1024 / 4) / 256, 256>>>(Scls, out);
}

// round 13
// speedup vs baseline: 1.4993x; 1.4993x over previous
#include <cuda_runtime.h>
#include <cuda_bf16.h>
#include <cstdint>
#include <cstddef>

typedef __nv_bfloat16 bf16;
#define NTOK 2048
#define HEADS 8
#define STAGES 3

// ---------------- scratch (static device globals) ----------------
__device__ float g_qkv_cls[(size_t)NTOK * 3072];
__device__ float g_qk_reg [(size_t)NTOK * 2048];
__device__ bf16  g_Xc[(size_t)NTOK * 2048];
__device__ bf16  g_Xr[(size_t)NTOK * 2048];
__device__ bf16  g_Wc[(size_t)3072 * 2048];
__device__ bf16  g_Wr[(size_t)2048 * 2048];
__device__ bf16  g_qc[(size_t)HEADS * NTOK * 256];
__device__ bf16  g_kc[(size_t)HEADS * NTOK * 256];
__device__ bf16  g_qr[(size_t)HEADS * NTOK * 256];
__device__ bf16  g_kr[(size_t)HEADS * NTOK * 256];
__device__ bf16  g_vn[(size_t)NTOK * 2048];             // [n][h*128+d], lo at +1024
__device__ bf16  g_Vt[(size_t)HEADS * 128 * 4096];
__device__ float g_Scls[(size_t)HEADS * NTOK * NTOK];   // scores; later reused for PV partials
__device__ float g_Sreg[(size_t)HEADS * NTOK * NTOK];
__device__ float g_Svv [(size_t)NTOK * NTOK];           // SUM over heads of vn.vn^T (symmetric)
__device__ bf16  g_P[(size_t)HEADS * NTOK * 4096];

// ---------------- helpers ----------------
__device__ __forceinline__ uint32_t s2u(const void* p) {
    uint32_t a;
    asm("{ .reg .u64 t; cvta.to.shared.u64 t, %1; cvt.u32.u64 %0, t; }" : "=r"(a) : "l"(p));
    return a;
}
#define SWZ(x) ((x) ^ (((x) >> 3) & 0x70))

__device__ __forceinline__ void cpasync16(uint32_t s, const void* g) {
    asm volatile("cp.async.cg.shared.global [%0], [%1], 16;" :: "r"(s), "l"(g) : "memory");
}
#define CP_COMMIT() asm volatile("cp.async.commit_group;" ::: "memory")
#define CP_WAIT(n)  asm volatile("cp.async.wait_group %0;" :: "n"(n) : "memory")

__device__ __forceinline__ void ldsm4(uint32_t& r0, uint32_t& r1, uint32_t& r2, uint32_t& r3, uint32_t a) {
    asm volatile("ldmatrix.sync.aligned.m8n8.x4.shared.b16 {%0,%1,%2,%3}, [%4];"
                 : "=r"(r0), "=r"(r1), "=r"(r2), "=r"(r3) : "r"(a));
}
__device__ __forceinline__ void mma16816(float* d, const uint32_t* a, uint32_t b0, uint32_t b1) {
    asm volatile(
        "mma.sync.aligned.m16n8k16.row.col.f32.bf16.bf16.f32 "
        "{%0,%1,%2,%3}, {%4,%5,%6,%7}, {%8,%9}, {%0,%1,%2,%3};"
        : "+f"(d[0]), "+f"(d[1]), "+f"(d[2]), "+f"(d[3])
        : "r"(a[0]), "r"(a[1]), "r"(a[2]), "r"(a[3]), "r"(b0), "r"(b1));
}

// ---------------- HMMA NT GEMM, per-mode tile selection (R11 layout, proven) ----------
// MODE 1: PV split-K  MW=1 (64x128, 3 CTA/SM)  grid 768:  z=x>>5 (head*3+seg), yt=x&31
// MODE 2: qkv merged  MW=1 (64x128, 3 CTA/SM)  grid 1280: x<768 cls tile (v-columns
//                     j0>=2048 ALSO write x_ori -> xout[:,1024:2048]), else reg tile
// MODE 3: scores+vv   MW=2 (128x128, 2 CTA/SM) grid 4232: x<136 vv symm tile FIRST
template<int MODE>
__global__ __launch_bounds__(256, (MODE == 3) ? 2 : 3) void hm_gemm_k(float* __restrict__ xout)
{
    extern __shared__ char dsm[];
    constexpr int MW = (MODE == 3) ? 2 : 1;
    constexpr int NT = 2 * MW;                     // n-tiles (of 8) per warp
    constexpr int NP = NT / 2;                     // b ldsm.x4 per warp
    constexpr int MROWS = MW * 64;
    constexpr uint32_t ABYTES = (uint32_t)MROWS * 128u;
    constexpr uint32_t STGB = ABYTES + 16384u;
    const size_t QH = (size_t)NTOK * 256, SH = (size_t)NTOK * NTOK;

    const bf16 *A, *B; float* C;
    int lda, ldb, ldc, K, i0, j0;
    bool symm = false; int bi = 0, bj = 0;
    bool singleseg = false, vcols = false;

    if (MODE == 2) {
        K = 1024; lda = 2048; ldb = 2048;
        const int t = blockIdx.x;
        if (t < 768) {
            A = g_Xc; B = g_Wc; C = g_qkv_cls; ldc = 3072;
            i0 = (t / 24) * 64;  j0 = (t % 24) * 128;
            vcols = (j0 >= 2048);
        } else {
            const int t2 = t - 768;
            A = g_Xr; B = g_Wr; C = g_qk_reg; ldc = 2048;
            i0 = (t2 >> 4) * 64;  j0 = (t2 & 15) * 128;
        }
    } else if (MODE == 3) {
        const int x = blockIdx.x;
        if (x < 136) {                 // vv long tiles first (LPT scheduling)
            symm = true;
            bi = (int)((33.0f - sqrtf(fmaxf(0.0f, 1089.0f - 8.0f * (float)x))) * 0.5f);
            while ((bi + 1) * (33 - (bi + 1)) / 2 <= x) bi++;
            while (bi * (33 - bi) / 2 > x) bi--;
            bj = bi + (x - bi * (33 - bi) / 2);
            i0 = bi * 128; j0 = bj * 128;
            A = g_vn; B = g_vn; C = g_Svv; lda = 2048; ldb = 2048; ldc = 2048; K = 1024;
        } else {
            const int t = x - 136;
            const int z = t >> 8, r = t & 255;
            K = 128; lda = 256; ldb = 256; ldc = 2048;
            if (z < 8) { A = g_qc + z * QH;       B = g_kc + z * QH;       C = g_Scls + z * SH; }
            else       { A = g_qr + (z - 8) * QH; B = g_kr + (z - 8) * QH; C = g_Sreg + (z - 8) * SH; }
            i0 = (r >> 4) * 128;  j0 = (r & 15) * 128;
        }
    } else {  // MODE 1: PV
        singleseg = true;
        const int z = blockIdx.x >> 5, yt = blockIdx.x & 31;
        const int head = z / 3, seg = z % 3;
        K = 2048;
        A = g_P  + (size_t)head * NTOK * 4096 + ((seg == 1) ? (size_t)K : 0);
        B = g_Vt + (size_t)head * 128  * 4096 + ((seg == 2) ? (size_t)K : 0);
        C = g_Scls + (size_t)z * NTOK * 128;
        lda = 4096; ldb = 4096; ldc = 128;
        i0 = yt * 64; j0 = 0;
    }

    const int nkc = K >> 6;
    const int NC  = singleseg ? nkc : 3 * nkc;
    const int tid = threadIdx.x;
    const uint32_t stage0 = (s2u(dsm) + 1023u) & ~1023u;

    const int lane = tid & 31, wid = tid >> 5;
    const int wm = wid % MW, wn = wid / MW;
    const int lt = lane >> 3, lr = lane & 7;
    const int arow = wm * 64 + (lt & 1) * 8 + lr;
    const int brow = wn * (NT * 8) + (lt & 1) * 8 + lr;
    const int kbsub = (lt >> 1) * 16;
    const uint32_t xm = (uint32_t)(lr << 4);

    float acc[4][NT][4];
#pragma unroll
    for (int i = 0; i < 4; i++)
#pragma unroll
        for (int j = 0; j < NT; j++)
#pragma unroll
            for (int q = 0; q < 4; q++) acc[i][j][q] = 0.0f;

    auto fill = [&](int s, int c) {
        const bf16 *Ab, *Bb;
        if (MODE == 1) {
            const int kk = c << 6;
            Ab = A + kk;  Bb = B + kk;
        } else {
            const int seg = c / nkc, kk = (c - seg * nkc) << 6;
            Ab = A + ((seg == 1) ? K : 0) + kk;
            Bb = B + ((seg == 2) ? K : 0) + kk;
        }
        const uint32_t sA = stage0 + (uint32_t)s * STGB, sB = sA + ABYTES;
#pragma unroll
        for (int i = 0; i < 2 * MW; i++) {
            const int id = (i << 8) + tid;
            const int row = id >> 3, c16 = id & 7;
            const uint32_t so = SWZ((uint32_t)((row << 7) + (c16 << 4)));
            cpasync16(sA + so, Ab + (size_t)(i0 + row) * lda + (c16 << 3));
        }
#pragma unroll
        for (int i = 0; i < 4; i++) {
            const int id = (i << 8) + tid;
            const int row = id >> 3, c16 = id & 7;
            const uint32_t so = SWZ((uint32_t)((row << 7) + (c16 << 4)));
            cpasync16(sB + so, Bb + (size_t)(j0 + row) * ldb + (c16 << 3));
        }
    };

#pragma unroll
    for (int c = 0; c < STAGES; c++) { fill(c, c); CP_COMMIT(); }

    for (int c = 0; c < NC; ++c) {
        const int s = c - (c / STAGES) * STAGES;
        CP_WAIT(1);
        __syncthreads();
        if (c >= 1) {
            const int cn = c + 2;
            if (cn < NC) fill(cn - (cn / STAGES) * STAGES, cn);
            CP_COMMIT();
        }
        const uint32_t sA = stage0 + (uint32_t)s * STGB, sB = sA + ABYTES;
#pragma unroll
        for (int ks = 0; ks < 4; ks++) {
            const uint32_t koff = ((uint32_t)(ks * 32 + kbsub)) ^ xm;
            uint32_t a[4][4], b[NP][4];
#pragma unroll
            for (int mt = 0; mt < 4; mt++)
                ldsm4(a[mt][0], a[mt][1], a[mt][2], a[mt][3],
                      sA + (uint32_t)((arow + mt * 16) << 7) + koff);
#pragma unroll
            for (int np = 0; np < NP; np++)
                ldsm4(b[np][0], b[np][1], b[np][2], b[np][3],
                      sB + (uint32_t)((brow + np * 16) << 7) + koff);
#pragma unroll
            for (int mt = 0; mt < 4; mt++)
#pragma unroll
                for (int nt = 0; nt < NT; nt++)
                    mma16816(acc[mt][nt], a[mt], b[nt >> 1][nt & 1], b[nt >> 1][(nt & 1) + 2]);
        }
    }

    const int rq = lane >> 2, cq = (lane & 3) * 2;
#pragma unroll
    for (int mt = 0; mt < 4; mt++) {
        const int row = i0 + wm * 64 + mt * 16 + rq;
#pragma unroll
        for (int nt = 0; nt < NT; nt++) {
            const int col = j0 + wn * (NT * 8) + nt * 8 + cq;
            const float2 v0 = make_float2(acc[mt][nt][0], acc[mt][nt][1]);
            const float2 v1 = make_float2(acc[mt][nt][2], acc[mt][nt][3]);
            *(float2*)(C + (size_t)row * ldc + col)       = v0;
            *(float2*)(C + (size_t)(row + 8) * ldc + col) = v1;
            if (MODE == 2 && vcols) {   // x_ori: out[:,1024:2048] = v-block of qkv_cls
                *(float2*)(xout + (size_t)row * 2048 + col - 1024)       = v0;
                *(float2*)(xout + (size_t)(row + 8) * 2048 + col - 1024) = v1;
            }
        }
    }

    // mirror off-diagonal vv tile via padded smem transpose (MODE 3 only, MW=2)
    if (MODE == 3) {
        if (symm && bi != bj) {
            float* smf = (float*)dsm;              // 128 x 133 fp32 = 68KB < DS2
            __syncthreads();
#pragma unroll
            for (int mt = 0; mt < 4; mt++) {
                const int r = wm * 64 + mt * 16 + rq;
#pragma unroll
                for (int nt = 0; nt < NT; nt++) {
                    const int cc = wn * (NT * 8) + nt * 8 + cq;
                    smf[r * 133 + cc]           = acc[mt][nt][0];
                    smf[r * 133 + cc + 1]       = acc[mt][nt][1];
                    smf[(r + 8) * 133 + cc]     = acc[mt][nt][2];
                    smf[(r + 8) * 133 + cc + 1] = acc[mt][nt][3];
                }
            }
            __syncthreads();
            const int r2 = tid & 127;
            const int c2b = (tid >> 7) * 64;
            float* Crow = C + (size_t)(j0 + r2) * ldc + i0 + c2b;
#pragma unroll
            for (int q = 0; q < 16; q++) {
                float4 v = make_float4(smf[(c2b + 4 * q + 0) * 133 + r2],
                                       smf[(c2b + 4 * q + 1) * 133 + r2],
                                       smf[(c2b + 4 * q + 2) * 133 + r2],
                                       smf[(c2b + 4 * q + 3) * 133 + r2]);
                *(float4*)(Crow + 4 * q) = v;
            }
        }
    }
}

// ---------------- PV split-K reduce (x_ori written by qkv epilogue now) ----------------
__global__ __launch_bounds__(256) void pv_finish(const float* __restrict__ part, float* __restrict__ out)
{
    const size_t t = (size_t)blockIdx.x * 256 + threadIdx.x;   // over 2048*1024/4
    const size_t e = t * 4;
    const int n = (int)(e >> 10), c = (int)(e & 1023);
    const int h = c >> 7, d = c & 127;
    const size_t base = (((size_t)h * 3 * NTOK) + n) * 128 + d;
    const size_t sg = (size_t)NTOK * 128;
    float4 v0 = *(const float4*)(part + base);
    float4 v1 = *(const float4*)(part + base + sg);
    float4 v2 = *(const float4*)(part + base + 2 * sg);
    *(float4*)(out + (size_t)n * 2048 + c) =
        make_float4(v0.x + v1.x + v2.x, v0.y + v1.y + v2.y,
                    v0.z + v1.z + v2.z, v0.w + v1.w + v2.w);
}

// ---------------- fp32 -> bf16 hi|lo split ----------------
__global__ __launch_bounds__(256) void split_x(const float* __restrict__ xc, const float* __restrict__ xr)
{
    const size_t i = (size_t)blockIdx.x * 256 + threadIdx.x;
    const int n = (int)(i >> 10), c = (int)(i & 1023);
    const float v = (blockIdx.z == 0 ? xc : xr)[i];
    bf16* o = (blockIdx.z == 0 ? g_Xc : g_Xr) + (size_t)n * 2048 + c;
    const bf16 h = __float2bfloat16(v);
    o[0] = h;  o[1024] = __float2bfloat16(v - __bfloat162float(h));
}

// ---------------- transpose + split: fp32 [R][C] -> bf16 [C][ldout], lo at +R ---------
__global__ __launch_bounds__(256) void transpose_split(
    const float* __restrict__ in, bf16* __restrict__ out,
    int R, int C, int ldin, int ldout, size_t zin, size_t zout)
{
    __shared__ float t[32][33];
    in  += (size_t)blockIdx.z * zin;
    out += (size_t)blockIdx.z * zout;
    const int r0 = blockIdx.y * 32, c0 = blockIdx.x * 32;
    const int tx = threadIdx.x & 31, ty = threadIdx.x >> 5;
#pragma unroll
    for (int i = 0; i < 4; i++)
        t[ty + i * 8][tx] = in[(size_t)(r0 + ty + i * 8) * ldin + c0 + tx];
    __syncthreads();
#pragma unroll
    for (int i = 0; i < 4; i++) {
        const int cc = ty + i * 8;
        const float v = t[tx][cc];
        const bf16 h = __float2bfloat16(v);
        out[(size_t)(c0 + cc) * ldout + r0 + tx]     = h;
        out[(size_t)(c0 + cc) * ldout + R + r0 + tx] = __float2bfloat16(v - __bfloat162float(h));
    }
}

// ---------------- L2-normalize + split ----------------
__global__ __launch_bounds__(256) void normalize_k()
{
    const int gid  = blockIdx.x * 8 + (threadIdx.x >> 5);
    const int lane = threadIdx.x & 31;
    const int op  = gid / (NTOK * HEADS);
    const int rem = gid - op * (NTOK * HEADS);
    const int n = rem >> 3, h = rem & 7;

    const float* src; bf16* dst; int lo_off;
    if (op == 0)      { src = g_qkv_cls + (size_t)n * 3072 + h * 128;        dst = g_qc + ((size_t)h * NTOK + n) * 256; lo_off = 128; }
    else if (op == 1) { src = g_qkv_cls + (size_t)n * 3072 + 1024 + h * 128; dst = g_kc + ((size_t)h * NTOK + n) * 256; lo_off = 128; }
    else if (op == 2) { src = g_qk_reg  + (size_t)n * 2048 + h * 128;        dst = g_qr + ((size_t)h * NTOK + n) * 256; lo_off = 128; }
    else if (op == 3) { src = g_qk_reg  + (size_t)n * 2048 + 1024 + h * 128; dst = g_kr + ((size_t)h * NTOK + n) * 256; lo_off = 128; }
    else              { src = g_qkv_cls + (size_t)n * 3072 + 2048 + h * 128; dst = g_vn + (size_t)n * 2048 + h * 128;   lo_off = 1024; }

    float4 v = *(const float4*)(src + lane * 4);
    float ss = v.x * v.x + v.y * v.y + v.z * v.z + v.w * v.w;
#pragma unroll
    for (int o = 16; o; o >>= 1) ss += __shfl_xor_sync(0xffffffffu, ss, o);
    const float r = 1.0f / sqrtf(ss);
    float a[4] = { v.x * r, v.y * r, v.z * r, v.w * r };
#pragma unroll
    for (int j = 0; j < 4; j++) {
        const bf16 h2 = __float2bfloat16(a[j]);
        dst[lane * 4 + j]          = h2;
        dst[lo_off + lane * 4 + j] = __float2bfloat16(a[j] - __bfloat162float(h2));
    }
}

// ---------------- FMA-only exp + block reductions ----------------
__device__ __forceinline__ float fast_exp(float x)
{
    float t = x * 1.4426950408889634f;
    t = fmaxf(t, -120.0f);
    float r = t + 12582912.0f;
    float f = t - (r - 12582912.0f);
    int   k = __float_as_int(r) - 0x4B400000;
    float p = 1.5403530393381609e-4f;
    p = fmaf(p, f, 1.3333558146428443e-3f);
    p = fmaf(p, f, 9.618129107628477e-3f);
    p = fmaf(p, f, 5.550410866482158e-2f);
    p = fmaf(p, f, 2.402265069591007e-1f);
    p = fmaf(p, f, 6.931471805599453e-1f);
    p = fmaf(p, f, 1.0f);
    return p * __int_as_float((k + 127) << 23);
}
__device__ __forceinline__ float block_max(float v, float* red)
{
#pragma unroll
    for (int o = 16; o; o >>= 1) v = fmaxf(v, __shfl_xor_sync(0xffffffffu, v, o));
    if ((threadIdx.x & 31) == 0) red[threadIdx.x >> 5] = v;
    __syncthreads();
    float r = red[0];
#pragma unroll
    for (int i = 1; i < 8; i++) r = fmaxf(r, red[i]);
    __syncthreads();
    return r;
}
__device__ __forceinline__ float block_sum(float v, float* red)
{
#pragma unroll
    for (int o = 16; o; o >>= 1) v += __shfl_xor_sync(0xffffffffu, v, o);
    if ((threadIdx.x & 31) == 0) red[threadIdx.x >> 5] = v;
    __syncthreads();
    float r = red[0];
#pragma unroll
    for (int i = 1; i < 8; i++) r += red[i];
    __syncthreads();
    return r;
}
// joint (a,b) block sum with a single barrier
__device__ __forceinline__ void block_sum2(float& a, float& b, float* red2)
{
#pragma unroll
    for (int o = 16; o; o >>= 1) {
        a += __shfl_xor_sync(0xffffffffu, a, o);
        b += __shfl_xor_sync(0xffffffffu, b, o);
    }
    if ((threadIdx.x & 31) == 0) {
        red2[(threadIdx.x >> 5) * 2]     = a;
        red2[(threadIdx.x >> 5) * 2 + 1] = b;
    }
    __syncthreads();
    float ra = red2[0], rb = red2[1];
#pragma unroll
    for (int i = 1; i < 8; i++) { ra += red2[i * 2]; rb += red2[i * 2 + 1]; }
    __syncthreads();
    a = ra; b = rb;
}

// ---------------- fused masked dual softmax + combine + sim_round2 -----------------
__global__ __launch_bounds__(256) void row_fuse(
    const float* __restrict__ cls_score, const float* __restrict__ fg_score,
    float* __restrict__ out_sim)
{
    const int n = blockIdx.x;
    const int tid = threadIdx.x;
    const int m0 = tid * 8;
    __shared__ float s_sc[NTOK];
    __shared__ float red[16];

    float fc[8], fr[8];
    float lsc = -1e30f, lfs = -1e30f;
#pragma unroll
    for (int j = 0; j < 8; j++) {
        const int m = m0 + j;
        const float a = cls_score[m], b = fg_score[m];
        fc[j] = a;  fr[j] = b;
        s_sc[m] = a;
        lsc = fmaxf(lsc, a);  lfs = fmaxf(lfs, b);
    }
    __syncthreads();
    const float Mc = 25.0f * block_max(lsc, red) + 1.0f;
    const float Mr = 25.0f * block_max(lfs, red) + 1.0f;
    const float cthr = s_sc[n] - 0.1f;
    const float fthr = fg_score[n] - 0.1f;
#pragma unroll
    for (int j = 0; j < 8; j++) {
        fc[j] = (fc[j] > cthr) ? 25.0f * fc[j] : 0.0f;
        fr[j] = (fr[j] > fthr) ? 25.0f * fr[j] : 0.0f;
    }

    float vvacc[8];
    {
        float4 v0 = *(const float4*)(g_Svv + (size_t)n * NTOK + m0);
        float4 v1 = *(const float4*)(g_Svv + (size_t)n * NTOK + m0 + 4);
        vvacc[0] = v0.x; vvacc[1] = v0.y; vvacc[2] = v0.z; vvacc[3] = v0.w;
        vvacc[4] = v1.x; vvacc[5] = v1.y; vvacc[6] = v1.z; vvacc[7] = v1.w;
    }

    float simacc[8];
#pragma unroll
    for (int j = 0; j < 8; j++) simacc[j] = 0.0f;

    for (int h = 0; h < HEADS; h++) {
        const size_t base = ((size_t)h * NTOK + n) * NTOK + m0;
        bf16* Pb = g_P + ((size_t)h * NTOK + n) * 4096 + m0;
        float ec[8], er[8];

        float4 s0 = *(const float4*)(g_Scls + base);
        float4 s1 = *(const float4*)(g_Scls + base + 4);
        ec[0] = fast_exp(s0.x * fc[0] - Mc);  ec[1] = fast_exp(s0.y * fc[1] - Mc);
        ec[2] = fast_exp(s0.z * fc[2] - Mc);  ec[3] = fast_exp(s0.w * fc[3] - Mc);
        ec[4] = fast_exp(s1.x * fc[4] - Mc);  ec[5] = fast_exp(s1.y * fc[5] - Mc);
        ec[6] = fast_exp(s1.z * fc[6] - Mc);  ec[7] = fast_exp(s1.w * fc[7] - Mc);
        float smc = ec[0] + ec[1] + ec[2] + ec[3] + ec[4] + ec[5] + ec[6] + ec[7];

        float4 r0 = *(const float4*)(g_Sreg + base);
        float4 r1 = *(const float4*)(g_Sreg + base + 4);
        er[0] = fast_exp(r0.x * fr[0] - Mr);  er[1] = fast_exp(r0.y * fr[1] - Mr);
        er[2] = fast_exp(r0.z * fr[2] - Mr);  er[3] = fast_exp(r0.w * fr[3] - Mr);
        er[4] = fast_exp(r1.x * fr[4] - Mr);  er[5] = fast_exp(r1.y * fr[5] - Mr);
        er[6] = fast_exp(r1.z * fr[6] - Mr);  er[7] = fast_exp(r1.w * fr[7] - Mr);
        float smr = er[0] + er[1] + er[2] + er[3] + er[4] + er[5] + er[6] + er[7];

        block_sum2(smc, smr, red);             // one barrier for both sums
        const float ic = 0.5f / smc, ir = 0.5f / smr;

        float pv[8];
#pragma unroll
        for (int j = 0; j < 8; j++) pv[j] = ec[j] * ic + er[j] * ir;

        union { __nv_bfloat162 h2[4]; uint4 u; } ph, pl;
#pragma unroll
        for (int j = 0; j < 4; j++) {
            const bf16 h0 = __float2bfloat16(pv[2 * j]);
            const bf16 h1 = __float2bfloat16(pv[2 * j + 1]);
            ph.h2[j] = __nv_bfloat162(h0, h1);
            pl.h2[j] = __nv_bfloat162(
                __float2bfloat16(pv[2 * j]     - __bfloat162float(h0)),
                __float2bfloat16(pv[2 * j + 1] - __bfloat162float(h1)));
        }
        *(uint4*)(Pb)        = ph.u;
        *(uint4*)(Pb + 2048) = pl.u;

#pragma unroll
        for (int j = 0; j < 8; j++) simacc[j] += pv[j];
    }

    float sm = 0.0f;
#pragma unroll
    for (int j = 0; j < 8; j++) { simacc[j] = fast_exp(simacc[j] * 0.125f - 1.0f); sm += simacc[j]; }
    sm = block_sum(sm, red);
    float msum = 0.0f;
#pragma unroll
    for (int j = 0; j < 8; j++) {
        const float soft = simacc[j] / sm;
        const float keep = (vvacc[j] > 6.0f) ? soft : 0.0f;
        simacc[j] = keep; msum += keep;
    }
    msum = block_sum(msum, red);
    const float rn = 1.0f / msum;
    float4 o0 = make_float4(simacc[0] * rn, simacc[1] * rn, simacc[2] * rn, simacc[3] * rn);
    float4 o1 = make_float4(simacc[4] * rn, simacc[5] * rn, simacc[6] * rn, simacc[7] * rn);
    *(float4*)(out_sim + (size_t)n * NTOK + m0)     = o0;
    *(float4*)(out_sim + (size_t)n * NTOK + m0 + 4) = o1;
}

// -------------------------------- launch ----------------------------------------
extern "C" void kernel_launch(void* const* d_in, const int* in_sizes, int n_in,
                              void* d_out, int out_size)
{
    (void)in_sizes; (void)n_in; (void)out_size;
    const float* x_cls     = (const float*)d_in[0];
    const float* x_reg     = (const float*)d_in[1];
    const float* cls_score = (const float*)d_in[2];
    const float* fg_score  = (const float*)d_in[3];
    const float* W_cls     = (const float*)d_in[4];
    const float* W_reg     = (const float*)d_in[5];
    float* out = (float*)d_out;

    float *qkv_cls, *Scls;
    bf16 *Wc, *Wr, *Vt;
    cudaGetSymbolAddress((void**)&qkv_cls, g_qkv_cls);
    cudaGetSymbolAddress((void**)&Wc, g_Wc);
    cudaGetSymbolAddress((void**)&Wr, g_Wr);
    cudaGetSymbolAddress((void**)&Vt, g_Vt);
    cudaGetSymbolAddress((void**)&Scls, g_Scls);

    const int DS1 = STAGES * 24576 + 1024;   // MW=1 stages (64x128), 3 CTAs/SM
    const int DS2 = STAGES * 32768 + 1024;   // MW=2 stages (128x128), 2 CTAs/SM
    cudaFuncSetAttribute((const void*)hm_gemm_k<1>, cudaFuncAttributeMaxDynamicSharedMemorySize, DS1);
    cudaFuncSetAttribute((const void*)hm_gemm_k<2>, cudaFuncAttributeMaxDynamicSharedMemorySize, DS1);
    cudaFuncSetAttribute((const void*)hm_gemm_k<3>, cudaFuncAttributeMaxDynamicSharedMemorySize, DS2);

    // 1) split inputs, transpose+split weights (R11 prep kernels)
    split_x<<<dim3(8192, 1, 2), 256>>>(x_cls, x_reg);
    transpose_split<<<dim3(96, 32, 1), 256>>>(W_cls, Wc, 1024, 3072, 3072, 2048, 0, 0);
    transpose_split<<<dim3(64, 32, 1), 256>>>(W_reg, Wr, 1024, 2048, 3072, 2048, 0, 0);

    // 2) qkv projections (cls v-columns also write x_ori -> out[:,1024:2048])
    hm_gemm_k<2><<<1280, 256, DS1>>>(out);

    // 3) normalize q/k/v; transpose v -> Vt split
    normalize_k<<<5 * NTOK * HEADS / 8, 256>>>();
    transpose_split<<<dim3(4, 64, 8), 256>>>(qkv_cls + 2048, Vt, 2048, 128, 3072, 4096,
                                             128, (size_t)128 * 4096);

    // 4) scores (16 planes) + symmetric vv, 128x128 tiles @ 2 CTA/SM, vv LPT-first
    hm_gemm_k<3><<<4232, 256, DS2>>>(nullptr);

    // 5) fused softmax + sim (reads S*, writes P bf16 hi|lo + sim output)
    row_fuse<<<NTOK, 256>>>(cls_score, fg_score, out + (size_t)NTOK * NTOK);

    // 6) x = P @ V split-K partials (reuse g_Scls), then reduce -> out[:,0:1024]
    hm_gemm_k<1><<<768, 256, DS1>>>(nullptr);
    pv_finish<<<(NTOK * 1024 / 4) / 256, 256>>>(Scls, out);
}

// round 14
// speedup vs baseline: 1.5593x; 1.0400x over previous
#include <cuda_runtime.h>
#include <cuda_bf16.h>
#include <cstdint>
#include <cstddef>

typedef __nv_bfloat16 bf16;
#define NTOK 2048
#define HEADS 8
#define STAGES 3

// ---------------- scratch (static device globals) ----------------
__device__ float g_qkv_cls[(size_t)NTOK * 3072];
__device__ float g_qk_reg [(size_t)NTOK * 2048];
__device__ bf16  g_Xc[(size_t)NTOK * 2048];
__device__ bf16  g_Xr[(size_t)NTOK * 2048];
__device__ bf16  g_Wc[(size_t)3072 * 2048];
__device__ bf16  g_Wr[(size_t)2048 * 2048];
__device__ bf16  g_qc[(size_t)HEADS * NTOK * 256];
__device__ bf16  g_kc[(size_t)HEADS * NTOK * 256];
__device__ bf16  g_qr[(size_t)HEADS * NTOK * 256];
__device__ bf16  g_kr[(size_t)HEADS * NTOK * 256];
__device__ bf16  g_vn[(size_t)NTOK * 2048];             // [n][h*128+d] hi (lo half unused now)
__device__ bf16  g_Vt[(size_t)HEADS * 128 * 4096];
__device__ float g_Scls[(size_t)HEADS * NTOK * NTOK];   // scores; later reused for PV partials
__device__ float g_Sreg[(size_t)HEADS * NTOK * NTOK];
__device__ float g_Svv [(size_t)NTOK * NTOK];           // SUM over heads of vn.vn^T (mask only)
__device__ bf16  g_P[(size_t)HEADS * NTOK * 4096];

// ---------------- helpers ----------------
__device__ __forceinline__ uint32_t s2u(const void* p) {
    uint32_t a;
    asm("{ .reg .u64 t; cvta.to.shared.u64 t, %1; cvt.u32.u64 %0, t; }" : "=r"(a) : "l"(p));
    return a;
}
#define SWZ(x) ((x) ^ (((x) >> 3) & 0x70))

__device__ __forceinline__ void cpasync16(uint32_t s, const void* g) {
    asm volatile("cp.async.cg.shared.global [%0], [%1], 16;" :: "r"(s), "l"(g) : "memory");
}
#define CP_COMMIT() asm volatile("cp.async.commit_group;" ::: "memory")
#define CP_WAIT(n)  asm volatile("cp.async.wait_group %0;" :: "n"(n) : "memory")

__device__ __forceinline__ void ldsm4(uint32_t& r0, uint32_t& r1, uint32_t& r2, uint32_t& r3, uint32_t a) {
    asm volatile("ldmatrix.sync.aligned.m8n8.x4.shared.b16 {%0,%1,%2,%3}, [%4];"
                 : "=r"(r0), "=r"(r1), "=r"(r2), "=r"(r3) : "r"(a));
}
__device__ __forceinline__ void mma16816(float* d, const uint32_t* a, uint32_t b0, uint32_t b1) {
    asm volatile(
        "mma.sync.aligned.m16n8k16.row.col.f32.bf16.bf16.f32 "
        "{%0,%1,%2,%3}, {%4,%5,%6,%7}, {%8,%9}, {%0,%1,%2,%3};"
        : "+f"(d[0]), "+f"(d[1]), "+f"(d[2]), "+f"(d[3])
        : "r"(a[0]), "r"(a[1]), "r"(a[2]), "r"(a[3]), "r"(b0), "r"(b1));
}

// ---------------- HMMA NT GEMM, per-mode tile selection (R13 layout, proven) ----------
// MODE 1: PV split-K  MW=1 (64x128, 3 CTA/SM)  grid 768:  z=x>>5 (head*3+seg), yt=x&31
// MODE 2: qkv merged  MW=1 (64x128, 3 CTA/SM)  grid 1280: x<768 cls tile (v-columns
//                     j0>=2048 ALSO write x_ori -> xout[:,1024:2048]), else reg tile
// MODE 3: scores+vv   MW=2 (128x128, 2 CTA/SM) grid 4232: x<136 vv symm tile FIRST;
//                     vv is SINGLE-SEGMENT (hi.hi only) -- feeds only the >6 mask.
template<int MODE>
__global__ __launch_bounds__(256, (MODE == 3) ? 2 : 3) void hm_gemm_k(float* __restrict__ xout)
{
    extern __shared__ char dsm[];
    constexpr int MW = (MODE == 3) ? 2 : 1;
    constexpr int NT = 2 * MW;                     // n-tiles (of 8) per warp
    constexpr int NP = NT / 2;                     // b ldsm.x4 per warp
    constexpr int MROWS = MW * 64;
    constexpr uint32_t ABYTES = (uint32_t)MROWS * 128u;
    constexpr uint32_t STGB = ABYTES + 16384u;
    const size_t QH = (size_t)NTOK * 256, SH = (size_t)NTOK * NTOK;

    const bf16 *A, *B; float* C;
    int lda, ldb, ldc, K, i0, j0;
    bool symm = false; int bi = 0, bj = 0;
    bool singleseg = false, vcols = false;

    if (MODE == 2) {
        K = 1024; lda = 2048; ldb = 2048;
        const int t = blockIdx.x;
        if (t < 768) {
            A = g_Xc; B = g_Wc; C = g_qkv_cls; ldc = 3072;
            i0 = (t / 24) * 64;  j0 = (t % 24) * 128;
            vcols = (j0 >= 2048);
        } else {
            const int t2 = t - 768;
            A = g_Xr; B = g_Wr; C = g_qk_reg; ldc = 2048;
            i0 = (t2 >> 4) * 64;  j0 = (t2 & 15) * 128;
        }
    } else if (MODE == 3) {
        const int x = blockIdx.x;
        if (x < 136) {                 // vv long tiles first (LPT); single segment
            symm = true;  singleseg = true;
            bi = (int)((33.0f - sqrtf(fmaxf(0.0f, 1089.0f - 8.0f * (float)x))) * 0.5f);
            while ((bi + 1) * (33 - (bi + 1)) / 2 <= x) bi++;
            while (bi * (33 - bi) / 2 > x) bi--;
            bj = bi + (x - bi * (33 - bi) / 2);
            i0 = bi * 128; j0 = bj * 128;
            A = g_vn; B = g_vn; C = g_Svv; lda = 2048; ldb = 2048; ldc = 2048; K = 1024;
        } else {
            const int t = x - 136;
            const int z = t >> 8, r = t & 255;
            K = 128; lda = 256; ldb = 256; ldc = 2048;
            if (z < 8) { A = g_qc + z * QH;       B = g_kc + z * QH;       C = g_Scls + z * SH; }
            else       { A = g_qr + (z - 8) * QH; B = g_kr + (z - 8) * QH; C = g_Sreg + (z - 8) * SH; }
            i0 = (r >> 4) * 128;  j0 = (r & 15) * 128;
        }
    } else {  // MODE 1: PV
        singleseg = true;
        const int z = blockIdx.x >> 5, yt = blockIdx.x & 31;
        const int head = z / 3, seg = z % 3;
        K = 2048;
        A = g_P  + (size_t)head * NTOK * 4096 + ((seg == 1) ? (size_t)K : 0);
        B = g_Vt + (size_t)head * 128  * 4096 + ((seg == 2) ? (size_t)K : 0);
        C = g_Scls + (size_t)z * NTOK * 128;
        lda = 4096; ldb = 4096; ldc = 128;
        i0 = yt * 64; j0 = 0;
    }

    const int nkc = K >> 6;
    const int NC  = singleseg ? nkc : 3 * nkc;
    const int tid = threadIdx.x;
    const uint32_t stage0 = (s2u(dsm) + 1023u) & ~1023u;

    const int lane = tid & 31, wid = tid >> 5;
    const int wm = wid % MW, wn = wid / MW;
    const int lt = lane >> 3, lr = lane & 7;
    const int arow = wm * 64 + (lt & 1) * 8 + lr;
    const int brow = wn * (NT * 8) + (lt & 1) * 8 + lr;
    const int kbsub = (lt >> 1) * 16;
    const uint32_t xm = (uint32_t)(lr << 4);

    float acc[4][NT][4];
#pragma unroll
    for (int i = 0; i < 4; i++)
#pragma unroll
        for (int j = 0; j < NT; j++)
#pragma unroll
            for (int q = 0; q < 4; q++) acc[i][j][q] = 0.0f;

    auto fill = [&](int s, int c) {
        const bf16 *Ab, *Bb;
        if (singleseg) {
            const int kk = c << 6;
            Ab = A + kk;  Bb = B + kk;
        } else {
            const int seg = c / nkc, kk = (c - seg * nkc) << 6;
            Ab = A + ((seg == 1) ? K : 0) + kk;
            Bb = B + ((seg == 2) ? K : 0) + kk;
        }
        const uint32_t sA = stage0 + (uint32_t)s * STGB, sB = sA + ABYTES;
#pragma unroll
        for (int i = 0; i < 2 * MW; i++) {
            const int id = (i << 8) + tid;
            const int row = id >> 3, c16 = id & 7;
            const uint32_t so = SWZ((uint32_t)((row << 7) + (c16 << 4)));
            cpasync16(sA + so, Ab + (size_t)(i0 + row) * lda + (c16 << 3));
        }
#pragma unroll
        for (int i = 0; i < 4; i++) {
            const int id = (i << 8) + tid;
            const int row = id >> 3, c16 = id & 7;
            const uint32_t so = SWZ((uint32_t)((row << 7) + (c16 << 4)));
            cpasync16(sB + so, Bb + (size_t)(j0 + row) * ldb + (c16 << 3));
        }
    };

#pragma unroll
    for (int c = 0; c < STAGES; c++) { fill(c, c); CP_COMMIT(); }

    for (int c = 0; c < NC; ++c) {
        const int s = c - (c / STAGES) * STAGES;
        CP_WAIT(1);
        __syncthreads();
        if (c >= 1) {
            const int cn = c + 2;
            if (cn < NC) fill(cn - (cn / STAGES) * STAGES, cn);
            CP_COMMIT();
        }
        const uint32_t sA = stage0 + (uint32_t)s * STGB, sB = sA + ABYTES;
#pragma unroll
        for (int ks = 0; ks < 4; ks++) {
            const uint32_t koff = ((uint32_t)(ks * 32 + kbsub)) ^ xm;
            uint32_t a[4][4], b[NP][4];
#pragma unroll
            for (int mt = 0; mt < 4; mt++)
                ldsm4(a[mt][0], a[mt][1], a[mt][2], a[mt][3],
                      sA + (uint32_t)((arow + mt * 16) << 7) + koff);
#pragma unroll
            for (int np = 0; np < NP; np++)
                ldsm4(b[np][0], b[np][1], b[np][2], b[np][3],
                      sB + (uint32_t)((brow + np * 16) << 7) + koff);
#pragma unroll
            for (int mt = 0; mt < 4; mt++)
#pragma unroll
                for (int nt = 0; nt < NT; nt++)
                    mma16816(acc[mt][nt], a[mt], b[nt >> 1][nt & 1], b[nt >> 1][(nt & 1) + 2]);
        }
    }

    const int rq = lane >> 2, cq = (lane & 3) * 2;
#pragma unroll
    for (int mt = 0; mt < 4; mt++) {
        const int row = i0 + wm * 64 + mt * 16 + rq;
#pragma unroll
        for (int nt = 0; nt < NT; nt++) {
            const int col = j0 + wn * (NT * 8) + nt * 8 + cq;
            const float2 v0 = make_float2(acc[mt][nt][0], acc[mt][nt][1]);
            const float2 v1 = make_float2(acc[mt][nt][2], acc[mt][nt][3]);
            *(float2*)(C + (size_t)row * ldc + col)       = v0;
            *(float2*)(C + (size_t)(row + 8) * ldc + col) = v1;
            if (MODE == 2 && vcols) {   // x_ori: out[:,1024:2048] = v-block of qkv_cls
                *(float2*)(xout + (size_t)row * 2048 + col - 1024)       = v0;
                *(float2*)(xout + (size_t)(row + 8) * 2048 + col - 1024) = v1;
            }
        }
    }

    // mirror off-diagonal vv tile via padded smem transpose (MODE 3 only, MW=2)
    if (MODE == 3) {
        if (symm && bi != bj) {
            float* smf = (float*)dsm;              // 128 x 133 fp32 = 68KB < DS2
            __syncthreads();
#pragma unroll
            for (int mt = 0; mt < 4; mt++) {
                const int r = wm * 64 + mt * 16 + rq;
#pragma unroll
                for (int nt = 0; nt < NT; nt++) {
                    const int cc = wn * (NT * 8) + nt * 8 + cq;
                    smf[r * 133 + cc]           = acc[mt][nt][0];
                    smf[r * 133 + cc + 1]       = acc[mt][nt][1];
                    smf[(r + 8) * 133 + cc]     = acc[mt][nt][2];
                    smf[(r + 8) * 133 + cc + 1] = acc[mt][nt][3];
                }
            }
            __syncthreads();
            const int r2 = tid & 127;
            const int c2b = (tid >> 7) * 64;
            float* Crow = C + (size_t)(j0 + r2) * ldc + i0 + c2b;
#pragma unroll
            for (int q = 0; q < 16; q++) {
                float4 v = make_float4(smf[(c2b + 4 * q + 0) * 133 + r2],
                                       smf[(c2b + 4 * q + 1) * 133 + r2],
                                       smf[(c2b + 4 * q + 2) * 133 + r2],
                                       smf[(c2b + 4 * q + 3) * 133 + r2]);
                *(float4*)(Crow + 4 * q) = v;
            }
        }
    }
}

// ---------------- PV split-K reduce ----------------
__global__ __launch_bounds__(256) void pv_finish(const float* __restrict__ part, float* __restrict__ out)
{
    const size_t t = (size_t)blockIdx.x * 256 + threadIdx.x;   // over 2048*1024/4
    const size_t e = t * 4;
    const int n = (int)(e >> 10), c = (int)(e & 1023);
    const int h = c >> 7, d = c & 127;
    const size_t base = (((size_t)h * 3 * NTOK) + n) * 128 + d;
    const size_t sg = (size_t)NTOK * 128;
    float4 v0 = *(const float4*)(part + base);
    float4 v1 = *(const float4*)(part + base + sg);
    float4 v2 = *(const float4*)(part + base + 2 * sg);
    *(float4*)(out + (size_t)n * 2048 + c) =
        make_float4(v0.x + v1.x + v2.x, v0.y + v1.y + v2.y,
                    v0.z + v1.z + v2.z, v0.w + v1.w + v2.w);
}

// ---------------- fp32 -> bf16 hi|lo split, float4-vectorized ----------------
__global__ __launch_bounds__(256) void split_x(const float* __restrict__ xc, const float* __restrict__ xr)
{
    const size_t i = ((size_t)blockIdx.x * 256 + threadIdx.x) * 4;   // over 2048*1024
    const int n = (int)(i >> 10), c = (int)(i & 1023);
    const float4 v = *(const float4*)((blockIdx.z == 0 ? xc : xr) + i);
    bf16* o = (blockIdx.z == 0 ? g_Xc : g_Xr) + (size_t)n * 2048 + c;
    const float a[4] = { v.x, v.y, v.z, v.w };
    union { __nv_bfloat162 h2[2]; uint2 u; } ph, pl;
#pragma unroll
    for (int j = 0; j < 2; j++) {
        const bf16 h0 = __float2bfloat16(a[2 * j]);
        const bf16 h1 = __float2bfloat16(a[2 * j + 1]);
        ph.h2[j] = __nv_bfloat162(h0, h1);
        pl.h2[j] = __nv_bfloat162(
            __float2bfloat16(a[2 * j]     - __bfloat162float(h0)),
            __float2bfloat16(a[2 * j + 1] - __bfloat162float(h1)));
    }
    *(uint2*)(o)        = ph.u;
    *(uint2*)(o + 1024) = pl.u;
}

// ---------------- transpose+split body (shared by W prep and Vt) ----------------
__device__ __forceinline__ void tsplit_body(
    const float* __restrict__ in, bf16* __restrict__ out,
    int R, int ldin, int ldout, int r0, int c0)
{
    __shared__ float t[32][33];
    const int tx = threadIdx.x & 31, ty = threadIdx.x >> 5;
#pragma unroll
    for (int i = 0; i < 4; i++)
        t[ty + i * 8][tx] = in[(size_t)(r0 + ty + i * 8) * ldin + c0 + tx];
    __syncthreads();
#pragma unroll
    for (int i = 0; i < 4; i++) {
        const int cc = ty + i * 8;
        const float v = t[tx][cc];
        const bf16 h = __float2bfloat16(v);
        out[(size_t)(c0 + cc) * ldout + r0 + tx]     = h;
        out[(size_t)(c0 + cc) * ldout + R + r0 + tx] = __float2bfloat16(v - __bfloat162float(h));
    }
}

__global__ __launch_bounds__(256) void transpose_split(
    const float* __restrict__ in, bf16* __restrict__ out,
    int R, int ldin, int ldout)
{
    tsplit_body(in, out, R, ldin, ldout, blockIdx.y * 32, blockIdx.x * 32);
}

// ---------------- merged: L2-normalize+split (x<10240) OR Vt transpose tile ----------
__global__ __launch_bounds__(256) void norm_vt()
{
    if (blockIdx.x < 10240) {
        const int gid  = blockIdx.x * 8 + (threadIdx.x >> 5);
        const int lane = threadIdx.x & 31;
        const int op  = gid / (NTOK * HEADS);
        const int rem = gid - op * (NTOK * HEADS);
        const int n = rem >> 3, h = rem & 7;

        const float* src; bf16* dst; int lo_off;
        if (op == 0)      { src = g_qkv_cls + (size_t)n * 3072 + h * 128;        dst = g_qc + ((size_t)h * NTOK + n) * 256; lo_off = 128; }
        else if (op == 1) { src = g_qkv_cls + (size_t)n * 3072 + 1024 + h * 128; dst = g_kc + ((size_t)h * NTOK + n) * 256; lo_off = 128; }
        else if (op == 2) { src = g_qk_reg  + (size_t)n * 2048 + h * 128;        dst = g_qr + ((size_t)h * NTOK + n) * 256; lo_off = 128; }
        else if (op == 3) { src = g_qk_reg  + (size_t)n * 2048 + 1024 + h * 128; dst = g_kr + ((size_t)h * NTOK + n) * 256; lo_off = 128; }
        else              { src = g_qkv_cls + (size_t)n * 3072 + 2048 + h * 128; dst = g_vn + (size_t)n * 2048 + h * 128;   lo_off = 0; }

        float4 v = *(const float4*)(src + lane * 4);
        float ss = v.x * v.x + v.y * v.y + v.z * v.z + v.w * v.w;
#pragma unroll
        for (int o = 16; o; o >>= 1) ss += __shfl_xor_sync(0xffffffffu, ss, o);
        const float r = 1.0f / sqrtf(ss);
        float a[4] = { v.x * r, v.y * r, v.z * r, v.w * r };
#pragma unroll
        for (int j = 0; j < 4; j++) {
            const bf16 h2 = __float2bfloat16(a[j]);
            dst[lane * 4 + j] = h2;
            if (lo_off)   // v (op 4) needs no lo: vv GEMM is single-segment now
                dst[lo_off + lane * 4 + j] = __float2bfloat16(a[j] - __bfloat162float(h2));
        }
    } else {
        // Vt transpose tile: v-block of qkv_cls (fp32) -> Vt [h][d][n] bf16 hi|lo
        const int t2 = (int)blockIdx.x - 10240;        // 0..2047
        const int bz = t2 >> 8, rem = t2 & 255;
        const int by = rem >> 2, bx = rem & 3;
        tsplit_body(g_qkv_cls + 2048 + bz * 128, g_Vt + (size_t)bz * 128 * 4096,
                    2048, 3072, 4096, by * 32, bx * 32);
    }
}

// ---------------- FMA-only exp + block reductions ----------------
__device__ __forceinline__ float fast_exp(float x)
{
    float t = x * 1.4426950408889634f;
    t = fmaxf(t, -120.0f);
    float r = t + 12582912.0f;
    float f = t - (r - 12582912.0f);
    int   k = __float_as_int(r) - 0x4B400000;
    float p = 1.5403530393381609e-4f;
    p = fmaf(p, f, 1.3333558146428443e-3f);
    p = fmaf(p, f, 9.618129107628477e-3f);
    p = fmaf(p, f, 5.550410866482158e-2f);
    p = fmaf(p, f, 2.402265069591007e-1f);
    p = fmaf(p, f, 6.931471805599453e-1f);
    p = fmaf(p, f, 1.0f);
    return p * __int_as_float((k + 127) << 23);
}
__device__ __forceinline__ float block_max(float v, float* red)
{
#pragma unroll
    for (int o = 16; o; o >>= 1) v = fmaxf(v, __shfl_xor_sync(0xffffffffu, v, o));
    if ((threadIdx.x & 31) == 0) red[threadIdx.x >> 5] = v;
    __syncthreads();
    float r = red[0];
#pragma unroll
    for (int i = 1; i < 8; i++) r = fmaxf(r, red[i]);
    __syncthreads();
    return r;
}
__device__ __forceinline__ float block_sum(float v, float* red)
{
#pragma unroll
    for (int o = 16; o; o >>= 1) v += __shfl_xor_sync(0xffffffffu, v, o);
    if ((threadIdx.x & 31) == 0) red[threadIdx.x >> 5] = v;
    __syncthreads();
    float r = red[0];
#pragma unroll
    for (int i = 1; i < 8; i++) r += red[i];
    __syncthreads();
    return r;
}
__device__ __forceinline__ void block_sum2(float& a, float& b, float* red2)
{
#pragma unroll
    for (int o = 16; o; o >>= 1) {
        a += __shfl_xor_sync(0xffffffffu, a, o);
        b += __shfl_xor_sync(0xffffffffu, b, o);
    }
    if ((threadIdx.x & 31) == 0) {
        red2[(threadIdx.x >> 5) * 2]     = a;
        red2[(threadIdx.x >> 5) * 2 + 1] = b;
    }
    __syncthreads();
    float ra = red2[0], rb = red2[1];
#pragma unroll
    for (int i = 1; i < 8; i++) { ra += red2[i * 2]; rb += red2[i * 2 + 1]; }
    __syncthreads();
    a = ra; b = rb;
}

// ---------------- fused masked dual softmax + combine + sim_round2 -----------------
__global__ __launch_bounds__(256) void row_fuse(
    const float* __restrict__ cls_score, const float* __restrict__ fg_score,
    float* __restrict__ out_sim)
{
    const int n = blockIdx.x;
    const int tid = threadIdx.x;
    const int m0 = tid * 8;
    __shared__ float s_sc[NTOK];
    __shared__ float red[16];

    float fc[8], fr[8];
    float lsc = -1e30f, lfs = -1e30f;
#pragma unroll
    for (int j = 0; j < 8; j++) {
        const int m = m0 + j;
        const float a = cls_score[m], b = fg_score[m];
        fc[j] = a;  fr[j] = b;
        s_sc[m] = a;
        lsc = fmaxf(lsc, a);  lfs = fmaxf(lfs, b);
    }
    __syncthreads();
    const float Mc = 25.0f * block_max(lsc, red) + 1.0f;
    const float Mr = 25.0f * block_max(lfs, red) + 1.0f;
    const float cthr = s_sc[n] - 0.1f;
    const float fthr = fg_score[n] - 0.1f;
#pragma unroll
    for (int j = 0; j < 8; j++) {
        fc[j] = (fc[j] > cthr) ? 25.0f * fc[j] : 0.0f;
        fr[j] = (fr[j] > fthr) ? 25.0f * fr[j] : 0.0f;
    }

    float vvacc[8];
    {
        float4 v0 = *(const float4*)(g_Svv + (size_t)n * NTOK + m0);
        float4 v1 = *(const float4*)(g_Svv + (size_t)n * NTOK + m0 + 4);
        vvacc[0] = v0.x; vvacc[1] = v0.y; vvacc[2] = v0.z; vvacc[3] = v0.w;
        vvacc[4] = v1.x; vvacc[5] = v1.y; vvacc[6] = v1.z; vvacc[7] = v1.w;
    }

    float simacc[8];
#pragma unroll
    for (int j = 0; j < 8; j++) simacc[j] = 0.0f;

    for (int h = 0; h < HEADS; h++) {
        const size_t base = ((size_t)h * NTOK + n) * NTOK + m0;
        bf16* Pb = g_P + ((size_t)h * NTOK + n) * 4096 + m0;
        float ec[8], er[8];

        float4 s0 = *(const float4*)(g_Scls + base);
        float4 s1 = *(const float4*)(g_Scls + base + 4);
        ec[0] = fast_exp(s0.x * fc[0] - Mc);  ec[1] = fast_exp(s0.y * fc[1] - Mc);
        ec[2] = fast_exp(s0.z * fc[2] - Mc);  ec[3] = fast_exp(s0.w * fc[3] - Mc);
        ec[4] = fast_exp(s1.x * fc[4] - Mc);  ec[5] = fast_exp(s1.y * fc[5] - Mc);
        ec[6] = fast_exp(s1.z * fc[6] - Mc);  ec[7] = fast_exp(s1.w * fc[7] - Mc);
        float smc = ec[0] + ec[1] + ec[2] + ec[3] + ec[4] + ec[5] + ec[6] + ec[7];

        float4 r0 = *(const float4*)(g_Sreg + base);
        float4 r1 = *(const float4*)(g_Sreg + base + 4);
        er[0] = fast_exp(r0.x * fr[0] - Mr);  er[1] = fast_exp(r0.y * fr[1] - Mr);
        er[2] = fast_exp(r0.z * fr[2] - Mr);  er[3] = fast_exp(r0.w * fr[3] - Mr);
        er[4] = fast_exp(r1.x * fr[4] - Mr);  er[5] = fast_exp(r1.y * fr[5] - Mr);
        er[6] = fast_exp(r1.z * fr[6] - Mr);  er[7] = fast_exp(r1.w * fr[7] - Mr);
        float smr = er[0] + er[1] + er[2] + er[3] + er[4] + er[5] + er[6] + er[7];

        block_sum2(smc, smr, red);             // one barrier for both sums
        const float ic = 0.5f / smc, ir = 0.5f / smr;

        float pv[8];
#pragma unroll
        for (int j = 0; j < 8; j++) pv[j] = ec[j] * ic + er[j] * ir;

        union { __nv_bfloat162 h2[4]; uint4 u; } ph, pl;
#pragma unroll
        for (int j = 0; j < 4; j++) {
            const bf16 h0 = __float2bfloat16(pv[2 * j]);
            const bf16 h1 = __float2bfloat16(pv[2 * j + 1]);
            ph.h2[j] = __nv_bfloat162(h0, h1);
            pl.h2[j] = __nv_bfloat162(
                __float2bfloat16(pv[2 * j]     - __bfloat162float(h0)),
                __float2bfloat16(pv[2 * j + 1] - __bfloat162float(h1)));
        }
        *(uint4*)(Pb)        = ph.u;
        *(uint4*)(Pb + 2048) = pl.u;

#pragma unroll
        for (int j = 0; j < 8; j++) simacc[j] += pv[j];
    }

    float sm = 0.0f;
#pragma unroll
    for (int j = 0; j < 8; j++) { simacc[j] = fast_exp(simacc[j] * 0.125f - 1.0f); sm += simacc[j]; }
    sm = block_sum(sm, red);
    float msum = 0.0f;
#pragma unroll
    for (int j = 0; j < 8; j++) {
        const float soft = simacc[j] / sm;
        const float keep = (vvacc[j] > 6.0f) ? soft : 0.0f;
        simacc[j] = keep; msum += keep;
    }
    msum = block_sum(msum, red);
    const float rn = 1.0f / msum;
    float4 o0 = make_float4(simacc[0] * rn, simacc[1] * rn, simacc[2] * rn, simacc[3] * rn);
    float4 o1 = make_float4(simacc[4] * rn, simacc[5] * rn, simacc[6] * rn, simacc[7] * rn);
    *(float4*)(out_sim + (size_t)n * NTOK + m0)     = o0;
    *(float4*)(out_sim + (size_t)n * NTOK + m0 + 4) = o1;
}

// -------------------------------- launch ----------------------------------------
extern "C" void kernel_launch(void* const* d_in, const int* in_sizes, int n_in,
                              void* d_out, int out_size)
{
    (void)in_sizes; (void)n_in; (void)out_size;
    const float* x_cls     = (const float*)d_in[0];
    const float* x_reg     = (const float*)d_in[1];
    const float* cls_score = (const float*)d_in[2];
    const float* fg_score  = (const float*)d_in[3];
    const float* W_cls     = (const float*)d_in[4];
    const float* W_reg     = (const float*)d_in[5];
    float* out = (float*)d_out;

    float *Scls;
    bf16 *Wc, *Wr;
    cudaGetSymbolAddress((void**)&Wc, g_Wc);
    cudaGetSymbolAddress((void**)&Wr, g_Wr);
    cudaGetSymbolAddress((void**)&Scls, g_Scls);

    const int DS1 = STAGES * 24576 + 1024;   // MW=1 stages (64x128), 3 CTAs/SM
    const int DS2 = STAGES * 32768 + 1024;   // MW=2 stages (128x128), 2 CTAs/SM
    cudaFuncSetAttribute((const void*)hm_gemm_k<1>, cudaFuncAttributeMaxDynamicSharedMemorySize, DS1);
    cudaFuncSetAttribute((const void*)hm_gemm_k<2>, cudaFuncAttributeMaxDynamicSharedMemorySize, DS1);
    cudaFuncSetAttribute((const void*)hm_gemm_k<3>, cudaFuncAttributeMaxDynamicSharedMemorySize, DS2);

    // 1) split inputs (vectorized), transpose+split weights
    split_x<<<dim3(2048, 1, 2), 256>>>(x_cls, x_reg);
    transpose_split<<<dim3(96, 32, 1), 256>>>(W_cls, Wc, 1024, 3072, 2048);
    transpose_split<<<dim3(64, 32, 1), 256>>>(W_reg, Wr, 1024, 3072, 2048);

    // 2) qkv projections (cls v-columns also write x_ori -> out[:,1024:2048])
    hm_gemm_k<2><<<1280, 256, DS1>>>(out);

    // 3) normalize q/k/v + Vt transpose, merged into one launch
    norm_vt<<<10240 + 2048, 256>>>();

    // 4) scores (16 planes) + single-segment symmetric vv, vv LPT-first
    hm_gemm_k<3><<<4232, 256, DS2>>>(nullptr);

    // 5) fused softmax + sim (reads S*, writes P bf16 hi|lo + sim output)
    row_fuse<<<NTOK, 256>>>(cls_score, fg_score, out + (size_t)NTOK * NTOK);

    // 6) x = P @ V split-K partials (reuse g_Scls), then reduce -> out[:,0:1024]
    hm_gemm_k<1><<<768, 256, DS1>>>(nullptr);
    pv_finish<<<(NTOK * 1024 / 4) / 256, 256>>>(Scls, out);
}

// round 15
// speedup vs baseline: 1.5978x; 1.0247x over previous
#include <cuda_runtime.h>
#include <cuda_bf16.h>
#include <cstdint>
#include <cstddef>

typedef __nv_bfloat16 bf16;
#define NTOK 2048
#define HEADS 8
#define STAGES 3

// ---------------- scratch (static device globals) ----------------
__device__ float g_qkv_cls[(size_t)NTOK * 3072];
__device__ float g_qk_reg [(size_t)NTOK * 2048];
__device__ bf16  g_Xc[(size_t)NTOK * 2048];
__device__ bf16  g_Xr[(size_t)NTOK * 2048];
__device__ bf16  g_Wc[(size_t)3072 * 2048];
__device__ bf16  g_Wr[(size_t)2048 * 2048];
__device__ bf16  g_qc[(size_t)HEADS * NTOK * 256];
__device__ bf16  g_kc[(size_t)HEADS * NTOK * 256];
__device__ bf16  g_qr[(size_t)HEADS * NTOK * 256];
__device__ bf16  g_kr[(size_t)HEADS * NTOK * 256];
__device__ bf16  g_vn[(size_t)NTOK * 2048];             // [n][h*128+d] hi only
__device__ bf16  g_Vt[(size_t)HEADS * 128 * 4096];
__device__ float g_Scls[(size_t)HEADS * NTOK * NTOK];   // scores; later reused for PV partials
__device__ float g_Sreg[(size_t)HEADS * NTOK * NTOK];
__device__ bf16  g_Svv [(size_t)NTOK * NTOK];           // head-sum vn.vn^T, bf16 (mask only)
__device__ bf16  g_P[(size_t)HEADS * NTOK * 4096];

// ---------------- helpers ----------------
__device__ __forceinline__ uint32_t s2u(const void* p) {
    uint32_t a;
    asm("{ .reg .u64 t; cvta.to.shared.u64 t, %1; cvt.u32.u64 %0, t; }" : "=r"(a) : "l"(p));
    return a;
}
#define SWZ(x) ((x) ^ (((x) >> 3) & 0x70))

__device__ __forceinline__ void cpasync16(uint32_t s, const void* g) {
    asm volatile("cp.async.cg.shared.global [%0], [%1], 16;" :: "r"(s), "l"(g) : "memory");
}
#define CP_COMMIT() asm volatile("cp.async.commit_group;" ::: "memory")
#define CP_WAIT(n)  asm volatile("cp.async.wait_group %0;" :: "n"(n) : "memory")

__device__ __forceinline__ void ldsm4(uint32_t& r0, uint32_t& r1, uint32_t& r2, uint32_t& r3, uint32_t a) {
    asm volatile("ldmatrix.sync.aligned.m8n8.x4.shared.b16 {%0,%1,%2,%3}, [%4];"
                 : "=r"(r0), "=r"(r1), "=r"(r2), "=r"(r3) : "r"(a));
}
__device__ __forceinline__ void mma16816(float* d, const uint32_t* a, uint32_t b0, uint32_t b1) {
    asm volatile(
        "mma.sync.aligned.m16n8k16.row.col.f32.bf16.bf16.f32 "
        "{%0,%1,%2,%3}, {%4,%5,%6,%7}, {%8,%9}, {%0,%1,%2,%3};"
        : "+f"(d[0]), "+f"(d[1]), "+f"(d[2]), "+f"(d[3])
        : "r"(a[0]), "r"(a[1]), "r"(a[2]), "r"(a[3]), "r"(b0), "r"(b1));
}

// ---------------- HMMA NT GEMM, per-mode tile selection ----------------
// MODE 1: PV split-K  MW=1 (64x128, 3 CTA/SM)  grid 768:  z=x>>5 (head*3+seg), yt=x&31
// MODE 2: qkv merged  MW=1 (64x128, 3 CTA/SM)  grid 1280: x<768 cls tile (v-columns
//                     j0>=2048 ALSO write x_ori -> xout[:,1024:2048]), else reg tile
// MODE 3: scores+vv   MW=2 (128x128, 2 CTA/SM) grid 4232: x<136 vv symm tile FIRST;
//                     vv single-segment, bf16 output (mask only).
// Segment dispatch is compile-time for MODE 1/2 (runtime only for MODE 3's symm flag).
template<int MODE>
__global__ __launch_bounds__(256, (MODE == 3) ? 2 : 3) void hm_gemm_k(float* __restrict__ xout)
{
    extern __shared__ char dsm[];
    constexpr int MW = (MODE == 3) ? 2 : 1;
    constexpr int NT = 2 * MW;                     // n-tiles (of 8) per warp
    constexpr int NP = NT / 2;                     // b ldsm.x4 per warp
    constexpr int MROWS = MW * 64;
    constexpr uint32_t ABYTES = (uint32_t)MROWS * 128u;
    constexpr uint32_t STGB = ABYTES + 16384u;
    const size_t QH = (size_t)NTOK * 256, SH = (size_t)NTOK * NTOK;

    const bf16 *A, *B; float* C;
    int lda, ldb, ldc, K, i0, j0;
    bool symm = false; int bi = 0, bj = 0;
    bool vcols = false;

    if (MODE == 2) {
        K = 1024; lda = 2048; ldb = 2048;
        const int t = blockIdx.x;
        if (t < 768) {
            A = g_Xc; B = g_Wc; C = g_qkv_cls; ldc = 3072;
            i0 = (t / 24) * 64;  j0 = (t % 24) * 128;
            vcols = (j0 >= 2048);
        } else {
            const int t2 = t - 768;
            A = g_Xr; B = g_Wr; C = g_qk_reg; ldc = 2048;
            i0 = (t2 >> 4) * 64;  j0 = (t2 & 15) * 128;
        }
    } else if (MODE == 3) {
        const int x = blockIdx.x;
        if (x < 136) {                 // vv long tiles first (LPT); single segment
            symm = true;
            bi = (int)((33.0f - sqrtf(fmaxf(0.0f, 1089.0f - 8.0f * (float)x))) * 0.5f);
            while ((bi + 1) * (33 - (bi + 1)) / 2 <= x) bi++;
            while (bi * (33 - bi) / 2 > x) bi--;
            bj = bi + (x - bi * (33 - bi) / 2);
            i0 = bi * 128; j0 = bj * 128;
            A = g_vn; B = g_vn; C = nullptr; lda = 2048; ldb = 2048; ldc = 2048; K = 1024;
        } else {
            const int t = x - 136;
            const int z = t >> 8, r = t & 255;
            K = 128; lda = 256; ldb = 256; ldc = 2048;
            if (z < 8) { A = g_qc + z * QH;       B = g_kc + z * QH;       C = g_Scls + z * SH; }
            else       { A = g_qr + (z - 8) * QH; B = g_kr + (z - 8) * QH; C = g_Sreg + (z - 8) * SH; }
            i0 = (r >> 4) * 128;  j0 = (r & 15) * 128;
        }
    } else {  // MODE 1: PV
        const int z = blockIdx.x >> 5, yt = blockIdx.x & 31;
        const int head = z / 3, seg = z % 3;
        K = 2048;
        A = g_P  + (size_t)head * NTOK * 4096 + ((seg == 1) ? (size_t)K : 0);
        B = g_Vt + (size_t)head * 128  * 4096 + ((seg == 2) ? (size_t)K : 0);
        C = g_Scls + (size_t)z * NTOK * 128;
        lda = 4096; ldb = 4096; ldc = 128;
        i0 = yt * 64; j0 = 0;
    }

    const int nkc = K >> 6;
    const int NC  = (MODE == 1) ? nkc : ((MODE == 3 && symm) ? nkc : 3 * nkc);
    const int tid = threadIdx.x;
    const uint32_t stage0 = (s2u(dsm) + 1023u) & ~1023u;

    const int lane = tid & 31, wid = tid >> 5;
    const int wm = wid % MW, wn = wid / MW;
    const int lt = lane >> 3, lr = lane & 7;
    const int arow = wm * 64 + (lt & 1) * 8 + lr;
    const int brow = wn * (NT * 8) + (lt & 1) * 8 + lr;
    const int kbsub = (lt >> 1) * 16;
    const uint32_t xm = (uint32_t)(lr << 4);

    float acc[4][NT][4];
#pragma unroll
    for (int i = 0; i < 4; i++)
#pragma unroll
        for (int j = 0; j < NT; j++)
#pragma unroll
            for (int q = 0; q < 4; q++) acc[i][j][q] = 0.0f;

    auto fill = [&](int s, int c) {
        const bf16 *Ab, *Bb;
        if (MODE == 1) {                               // compile-time: always single-seg
            const int kk = c << 6;
            Ab = A + kk;  Bb = B + kk;
        } else if (MODE == 3 && symm) {                // runtime only in MODE 3
            const int kk = c << 6;
            Ab = A + kk;  Bb = B + kk;
        } else {
            const int seg = c / nkc, kk = (c - seg * nkc) << 6;
            Ab = A + ((seg == 1) ? K : 0) + kk;
            Bb = B + ((seg == 2) ? K : 0) + kk;
        }
        const uint32_t sA = stage0 + (uint32_t)s * STGB, sB = sA + ABYTES;
#pragma unroll
        for (int i = 0; i < 2 * MW; i++) {
            const int id = (i << 8) + tid;
            const int row = id >> 3, c16 = id & 7;
            const uint32_t so = SWZ((uint32_t)((row << 7) + (c16 << 4)));
            cpasync16(sA + so, Ab + (size_t)(i0 + row) * lda + (c16 << 3));
        }
#pragma unroll
        for (int i = 0; i < 4; i++) {
            const int id = (i << 8) + tid;
            const int row = id >> 3, c16 = id & 7;
            const uint32_t so = SWZ((uint32_t)((row << 7) + (c16 << 4)));
            cpasync16(sB + so, Bb + (size_t)(j0 + row) * ldb + (c16 << 3));
        }
    };

#pragma unroll
    for (int c = 0; c < STAGES; c++) { fill(c, c); CP_COMMIT(); }

    for (int c = 0; c < NC; ++c) {
        const int s = c - (c / STAGES) * STAGES;
        CP_WAIT(1);
        __syncthreads();
        if (c >= 1) {
            const int cn = c + 2;
            if (cn < NC) fill(cn - (cn / STAGES) * STAGES, cn);
            CP_COMMIT();
        }
        const uint32_t sA = stage0 + (uint32_t)s * STGB, sB = sA + ABYTES;
#pragma unroll
        for (int ks = 0; ks < 4; ks++) {
            const uint32_t koff = ((uint32_t)(ks * 32 + kbsub)) ^ xm;
            uint32_t a[4][4], b[NP][4];
#pragma unroll
            for (int mt = 0; mt < 4; mt++)
                ldsm4(a[mt][0], a[mt][1], a[mt][2], a[mt][3],
                      sA + (uint32_t)((arow + mt * 16) << 7) + koff);
#pragma unroll
            for (int np = 0; np < NP; np++)
                ldsm4(b[np][0], b[np][1], b[np][2], b[np][3],
                      sB + (uint32_t)((brow + np * 16) << 7) + koff);
#pragma unroll
            for (int mt = 0; mt < 4; mt++)
#pragma unroll
                for (int nt = 0; nt < NT; nt++)
                    mma16816(acc[mt][nt], a[mt], b[nt >> 1][nt & 1], b[nt >> 1][(nt & 1) + 2]);
        }
    }

    const int rq = lane >> 2, cq = (lane & 3) * 2;
    if (MODE == 3 && symm) {
        // vv: bf16 output (mask-only consumer)
#pragma unroll
        for (int mt = 0; mt < 4; mt++) {
            const int row = i0 + wm * 64 + mt * 16 + rq;
#pragma unroll
            for (int nt = 0; nt < NT; nt++) {
                const int col = j0 + wn * (NT * 8) + nt * 8 + cq;
                *(__nv_bfloat162*)(g_Svv + (size_t)row * 2048 + col) =
                    __nv_bfloat162(__float2bfloat16(acc[mt][nt][0]), __float2bfloat16(acc[mt][nt][1]));
                *(__nv_bfloat162*)(g_Svv + (size_t)(row + 8) * 2048 + col) =
                    __nv_bfloat162(__float2bfloat16(acc[mt][nt][2]), __float2bfloat16(acc[mt][nt][3]));
            }
        }
        if (bi != bj) {   // mirror via padded smem transpose
            float* smf = (float*)dsm;              // 128 x 133 fp32 = 68KB < DS2
            __syncthreads();
#pragma unroll
            for (int mt = 0; mt < 4; mt++) {
                const int r = wm * 64 + mt * 16 + rq;
#pragma unroll
                for (int nt = 0; nt < NT; nt++) {
                    const int cc = wn * (NT * 8) + nt * 8 + cq;
                    smf[r * 133 + cc]           = acc[mt][nt][0];
                    smf[r * 133 + cc + 1]       = acc[mt][nt][1];
                    smf[(r + 8) * 133 + cc]     = acc[mt][nt][2];
                    smf[(r + 8) * 133 + cc + 1] = acc[mt][nt][3];
                }
            }
            __syncthreads();
            const int r2 = tid & 127;
            const int c2b = (tid >> 7) * 64;
            bf16* Crow = g_Svv + (size_t)(j0 + r2) * 2048 + i0 + c2b;
#pragma unroll
            for (int q = 0; q < 16; q++) {
                union { __nv_bfloat162 h2[2]; uint2 u; } p;
                p.h2[0] = __nv_bfloat162(__float2bfloat16(smf[(c2b + 4 * q + 0) * 133 + r2]),
                                         __float2bfloat16(smf[(c2b + 4 * q + 1) * 133 + r2]));
                p.h2[1] = __nv_bfloat162(__float2bfloat16(smf[(c2b + 4 * q + 2) * 133 + r2]),
                                         __float2bfloat16(smf[(c2b + 4 * q + 3) * 133 + r2]));
                *(uint2*)(Crow + 4 * q) = p.u;
            }
        }
    } else {
#pragma unroll
        for (int mt = 0; mt < 4; mt++) {
            const int row = i0 + wm * 64 + mt * 16 + rq;
#pragma unroll
            for (int nt = 0; nt < NT; nt++) {
                const int col = j0 + wn * (NT * 8) + nt * 8 + cq;
                const float2 v0 = make_float2(acc[mt][nt][0], acc[mt][nt][1]);
                const float2 v1 = make_float2(acc[mt][nt][2], acc[mt][nt][3]);
                *(float2*)(C + (size_t)row * ldc + col)       = v0;
                *(float2*)(C + (size_t)(row + 8) * ldc + col) = v1;
                if (MODE == 2 && vcols) {   // x_ori: out[:,1024:2048] = v-block
                    *(float2*)(xout + (size_t)row * 2048 + col - 1024)       = v0;
                    *(float2*)(xout + (size_t)(row + 8) * 2048 + col - 1024) = v1;
                }
            }
        }
    }
}

// ---------------- PV split-K reduce ----------------
__global__ __launch_bounds__(256) void pv_finish(const float* __restrict__ part, float* __restrict__ out)
{
    const size_t t = (size_t)blockIdx.x * 256 + threadIdx.x;   // over 2048*1024/4
    const size_t e = t * 4;
    const int n = (int)(e >> 10), c = (int)(e & 1023);
    const int h = c >> 7, d = c & 127;
    const size_t base = (((size_t)h * 3 * NTOK) + n) * 128 + d;
    const size_t sg = (size_t)NTOK * 128;
    float4 v0 = *(const float4*)(part + base);
    float4 v1 = *(const float4*)(part + base + sg);
    float4 v2 = *(const float4*)(part + base + 2 * sg);
    *(float4*)(out + (size_t)n * 2048 + c) =
        make_float4(v0.x + v1.x + v2.x, v0.y + v1.y + v2.y,
                    v0.z + v1.z + v2.z, v0.w + v1.w + v2.w);
}

// ---------------- fp32 -> bf16 hi|lo split, float4-vectorized ----------------
__global__ __launch_bounds__(256) void split_x(const float* __restrict__ xc, const float* __restrict__ xr)
{
    const size_t i = ((size_t)blockIdx.x * 256 + threadIdx.x) * 4;   // over 2048*1024
    const int n = (int)(i >> 10), c = (int)(i & 1023);
    const float4 v = *(const float4*)((blockIdx.z == 0 ? xc : xr) + i);
    bf16* o = (blockIdx.z == 0 ? g_Xc : g_Xr) + (size_t)n * 2048 + c;
    const float a[4] = { v.x, v.y, v.z, v.w };
    union { __nv_bfloat162 h2[2]; uint2 u; } ph, pl;
#pragma unroll
    for (int j = 0; j < 2; j++) {
        const bf16 h0 = __float2bfloat16(a[2 * j]);
        const bf16 h1 = __float2bfloat16(a[2 * j + 1]);
        ph.h2[j] = __nv_bfloat162(h0, h1);
        pl.h2[j] = __nv_bfloat162(
            __float2bfloat16(a[2 * j]     - __bfloat162float(h0)),
            __float2bfloat16(a[2 * j + 1] - __bfloat162float(h1)));
    }
    *(uint2*)(o)        = ph.u;
    *(uint2*)(o + 1024) = pl.u;
}

// ---------------- transpose+split body ----------------
__device__ __forceinline__ void tsplit_body(
    const float* __restrict__ in, bf16* __restrict__ out,
    int R, int ldin, int ldout, int r0, int c0)
{
    __shared__ float t[32][33];
    const int tx = threadIdx.x & 31, ty = threadIdx.x >> 5;
#pragma unroll
    for (int i = 0; i < 4; i++)
        t[ty + i * 8][tx] = in[(size_t)(r0 + ty + i * 8) * ldin + c0 + tx];
    __syncthreads();
#pragma unroll
    for (int i = 0; i < 4; i++) {
        const int cc = ty + i * 8;
        const float v = t[tx][cc];
        const bf16 h = __float2bfloat16(v);
        out[(size_t)(c0 + cc) * ldout + r0 + tx]     = h;
        out[(size_t)(c0 + cc) * ldout + R + r0 + tx] = __float2bfloat16(v - __bfloat162float(h));
    }
}

// merged W_cls + W_reg transpose/split, one flat launch
__global__ __launch_bounds__(256) void w_prep(
    const float* __restrict__ Wcls, const float* __restrict__ Wreg)
{
    const int x = blockIdx.x;
    if (x < 3072) {
        tsplit_body(Wcls, g_Wc, 1024, 3072, 2048, (x / 96) * 32, (x % 96) * 32);
    } else {
        const int t2 = x - 3072;
        tsplit_body(Wreg, g_Wr, 1024, 3072, 2048, (t2 / 64) * 32, (t2 % 64) * 32);
    }
}

// ---------------- merged: L2-normalize+split (x<10240) OR Vt transpose tile ----------
__global__ __launch_bounds__(256) void norm_vt()
{
    if (blockIdx.x < 10240) {
        const int gid  = blockIdx.x * 8 + (threadIdx.x >> 5);
        const int lane = threadIdx.x & 31;
        const int op  = gid / (NTOK * HEADS);
        const int rem = gid - op * (NTOK * HEADS);
        const int n = rem >> 3, h = rem & 7;

        const float* src; bf16* dst; int lo_off;
        if (op == 0)      { src = g_qkv_cls + (size_t)n * 3072 + h * 128;        dst = g_qc + ((size_t)h * NTOK + n) * 256; lo_off = 128; }
        else if (op == 1) { src = g_qkv_cls + (size_t)n * 3072 + 1024 + h * 128; dst = g_kc + ((size_t)h * NTOK + n) * 256; lo_off = 128; }
        else if (op == 2) { src = g_qk_reg  + (size_t)n * 2048 + h * 128;        dst = g_qr + ((size_t)h * NTOK + n) * 256; lo_off = 128; }
        else if (op == 3) { src = g_qk_reg  + (size_t)n * 2048 + 1024 + h * 128; dst = g_kr + ((size_t)h * NTOK + n) * 256; lo_off = 128; }
        else              { src = g_qkv_cls + (size_t)n * 3072 + 2048 + h * 128; dst = g_vn + (size_t)n * 2048 + h * 128;   lo_off = 0; }

        float4 v = *(const float4*)(src + lane * 4);
        float ss = v.x * v.x + v.y * v.y + v.z * v.z + v.w * v.w;
#pragma unroll
        for (int o = 16; o; o >>= 1) ss += __shfl_xor_sync(0xffffffffu, ss, o);
        const float r = 1.0f / sqrtf(ss);
        float a[4] = { v.x * r, v.y * r, v.z * r, v.w * r };
#pragma unroll
        for (int j = 0; j < 4; j++) {
            const bf16 h2 = __float2bfloat16(a[j]);
            dst[lane * 4 + j] = h2;
            if (lo_off)
                dst[lo_off + lane * 4 + j] = __float2bfloat16(a[j] - __bfloat162float(h2));
        }
    } else {
        const int t2 = (int)blockIdx.x - 10240;        // 0..2047
        const int bz = t2 >> 8, rem = t2 & 255;
        const int by = rem >> 2, bx = rem & 3;
        tsplit_body(g_qkv_cls + 2048 + bz * 128, g_Vt + (size_t)bz * 128 * 4096,
                    2048, 3072, 4096, by * 32, bx * 32);
    }
}

// ---------------- FMA-only exp + block reductions ----------------
__device__ __forceinline__ float fast_exp(float x)
{
    float t = x * 1.4426950408889634f;
    t = fmaxf(t, -120.0f);
    float r = t + 12582912.0f;
    float f = t - (r - 12582912.0f);
    int   k = __float_as_int(r) - 0x4B400000;
    float p = 1.5403530393381609e-4f;
    p = fmaf(p, f, 1.3333558146428443e-3f);
    p = fmaf(p, f, 9.618129107628477e-3f);
    p = fmaf(p, f, 5.550410866482158e-2f);
    p = fmaf(p, f, 2.402265069591007e-1f);
    p = fmaf(p, f, 6.931471805599453e-1f);
    p = fmaf(p, f, 1.0f);
    return p * __int_as_float((k + 127) << 23);
}
__device__ __forceinline__ float block_max(float v, float* red)
{
#pragma unroll
    for (int o = 16; o; o >>= 1) v = fmaxf(v, __shfl_xor_sync(0xffffffffu, v, o));
    if ((threadIdx.x & 31) == 0) red[threadIdx.x >> 5] = v;
    __syncthreads();
    float r = red[0];
#pragma unroll
    for (int i = 1; i < 8; i++) r = fmaxf(r, red[i]);
    __syncthreads();
    return r;
}
__device__ __forceinline__ float block_sum(float v, float* red)
{
#pragma unroll
    for (int o = 16; o; o >>= 1) v += __shfl_xor_sync(0xffffffffu, v, o);
    if ((threadIdx.x & 31) == 0) red[threadIdx.x >> 5] = v;
    __syncthreads();
    float r = red[0];
#pragma unroll
    for (int i = 1; i < 8; i++) r += red[i];
    __syncthreads();
    return r;
}
__device__ __forceinline__ void block_sum2(float& a, float& b, float* red2)
{
#pragma unroll
    for (int o = 16; o; o >>= 1) {
        a += __shfl_xor_sync(0xffffffffu, a, o);
        b += __shfl_xor_sync(0xffffffffu, b, o);
    }
    if ((threadIdx.x & 31) == 0) {
        red2[(threadIdx.x >> 5) * 2]     = a;
        red2[(threadIdx.x >> 5) * 2 + 1] = b;
    }
    __syncthreads();
    float ra = red2[0], rb = red2[1];
#pragma unroll
    for (int i = 1; i < 8; i++) { ra += red2[i * 2]; rb += red2[i * 2 + 1]; }
    __syncthreads();
    a = ra; b = rb;
}

// ---------------- fused masked dual softmax + combine + sim_round2 -----------------
__global__ __launch_bounds__(256) void row_fuse(
    const float* __restrict__ cls_score, const float* __restrict__ fg_score,
    float* __restrict__ out_sim)
{
    const int n = blockIdx.x;
    const int tid = threadIdx.x;
    const int m0 = tid * 8;
    __shared__ float s_sc[NTOK];
    __shared__ float red[16];

    float fc[8], fr[8];
    float lsc = -1e30f, lfs = -1e30f;
#pragma unroll
    for (int j = 0; j < 8; j++) {
        const int m = m0 + j;
        const float a = cls_score[m], b = fg_score[m];
        fc[j] = a;  fr[j] = b;
        s_sc[m] = a;
        lsc = fmaxf(lsc, a);  lfs = fmaxf(lfs, b);
    }
    __syncthreads();
    const float Mc = 25.0f * block_max(lsc, red) + 1.0f;
    const float Mr = 25.0f * block_max(lfs, red) + 1.0f;
    const float cthr = s_sc[n] - 0.1f;
    const float fthr = fg_score[n] - 0.1f;
#pragma unroll
    for (int j = 0; j < 8; j++) {
        fc[j] = (fc[j] > cthr) ? 25.0f * fc[j] : 0.0f;
        fr[j] = (fr[j] > fthr) ? 25.0f * fr[j] : 0.0f;
    }

    float vvacc[8];
    {
        const uint4 u = *(const uint4*)(g_Svv + (size_t)n * NTOK + m0);  // 8 bf16
        const __nv_bfloat162* hv = (const __nv_bfloat162*)&u;
#pragma unroll
        for (int j = 0; j < 4; j++) {
            vvacc[2 * j]     = __bfloat162float(hv[j].x);
            vvacc[2 * j + 1] = __bfloat162float(hv[j].y);
        }
    }

    float simacc[8];
#pragma unroll
    for (int j = 0; j < 8; j++) simacc[j] = 0.0f;

    for (int h = 0; h < HEADS; h++) {
        const size_t base = ((size_t)h * NTOK + n) * NTOK + m0;
        bf16* Pb = g_P + ((size_t)h * NTOK + n) * 4096 + m0;
        float ec[8], er[8];

        float4 s0 = *(const float4*)(g_Scls + base);
        float4 s1 = *(const float4*)(g_Scls + base + 4);
        ec[0] = fast_exp(s0.x * fc[0] - Mc);  ec[1] = fast_exp(s0.y * fc[1] - Mc);
        ec[2] = fast_exp(s0.z * fc[2] - Mc);  ec[3] = fast_exp(s0.w * fc[3] - Mc);
        ec[4] = fast_exp(s1.x * fc[4] - Mc);  ec[5] = fast_exp(s1.y * fc[5] - Mc);
        ec[6] = fast_exp(s1.z * fc[6] - Mc);  ec[7] = fast_exp(s1.w * fc[7] - Mc);
        float smc = ec[0] + ec[1] + ec[2] + ec[3] + ec[4] + ec[5] + ec[6] + ec[7];

        float4 r0 = *(const float4*)(g_Sreg + base);
        float4 r1 = *(const float4*)(g_Sreg + base + 4);
        er[0] = fast_exp(r0.x * fr[0] - Mr);  er[1] = fast_exp(r0.y * fr[1] - Mr);
        er[2] = fast_exp(r0.z * fr[2] - Mr);  er[3] = fast_exp(r0.w * fr[3] - Mr);
        er[4] = fast_exp(r1.x * fr[4] - Mr);  er[5] = fast_exp(r1.y * fr[5] - Mr);
        er[6] = fast_exp(r1.z * fr[6] - Mr);  er[7] = fast_exp(r1.w * fr[7] - Mr);
        float smr = er[0] + er[1] + er[2] + er[3] + er[4] + er[5] + er[6] + er[7];

        block_sum2(smc, smr, red);
        const float ic = 0.5f / smc, ir = 0.5f / smr;

        float pv[8];
#pragma unroll
        for (int j = 0; j < 8; j++) pv[j] = ec[j] * ic + er[j] * ir;

        union { __nv_bfloat162 h2[4]; uint4 u; } ph, pl;
#pragma unroll
        for (int j = 0; j < 4; j++) {
            const bf16 h0 = __float2bfloat16(pv[2 * j]);
            const bf16 h1 = __float2bfloat16(pv[2 * j + 1]);
            ph.h2[j] = __nv_bfloat162(h0, h1);
            pl.h2[j] = __nv_bfloat162(
                __float2bfloat16(pv[2 * j]     - __bfloat162float(h0)),
                __float2bfloat16(pv[2 * j + 1] - __bfloat162float(h1)));
        }
        *(uint4*)(Pb)        = ph.u;
        *(uint4*)(Pb + 2048) = pl.u;

#pragma unroll
        for (int j = 0; j < 8; j++) simacc[j] += pv[j];
    }

    float sm = 0.0f;
#pragma unroll
    for (int j = 0; j < 8; j++) { simacc[j] = fast_exp(simacc[j] * 0.125f - 1.0f); sm += simacc[j]; }
    sm = block_sum(sm, red);
    float msum = 0.0f;
#pragma unroll
    for (int j = 0; j < 8; j++) {
        const float soft = simacc[j] / sm;
        const float keep = (vvacc[j] > 6.0f) ? soft : 0.0f;
        simacc[j] = keep; msum += keep;
    }
    msum = block_sum(msum, red);
    const float rn = 1.0f / msum;
    float4 o0 = make_float4(simacc[0] * rn, simacc[1] * rn, simacc[2] * rn, simacc[3] * rn);
    float4 o1 = make_float4(simacc[4] * rn, simacc[5] * rn, simacc[6] * rn, simacc[7] * rn);
    *(float4*)(out_sim + (size_t)n * NTOK + m0)     = o0;
    *(float4*)(out_sim + (size_t)n * NTOK + m0 + 4) = o1;
}

// -------------------------------- launch ----------------------------------------
extern "C" void kernel_launch(void* const* d_in, const int* in_sizes, int n_in,
                              void* d_out, int out_size)
{
    (void)in_sizes; (void)n_in; (void)out_size;
    const float* x_cls     = (const float*)d_in[0];
    const float* x_reg     = (const float*)d_in[1];
    const float* cls_score = (const float*)d_in[2];
    const float* fg_score  = (const float*)d_in[3];
    const float* W_cls     = (const float*)d_in[4];
    const float* W_reg     = (const float*)d_in[5];
    float* out = (float*)d_out;

    float* Scls;
    cudaGetSymbolAddress((void**)&Scls, g_Scls);

    const int DS1 = STAGES * 24576 + 1024;   // MW=1 stages (64x128), 3 CTAs/SM
    const int DS2 = STAGES * 32768 + 1024;   // MW=2 stages (128x128), 2 CTAs/SM
    cudaFuncSetAttribute((const void*)hm_gemm_k<1>, cudaFuncAttributeMaxDynamicSharedMemorySize, DS1);
    cudaFuncSetAttribute((const void*)hm_gemm_k<2>, cudaFuncAttributeMaxDynamicSharedMemorySize, DS1);
    cudaFuncSetAttribute((const void*)hm_gemm_k<3>, cudaFuncAttributeMaxDynamicSharedMemorySize, DS2);

    // 1) split inputs (vectorized); merged W transpose/split
    split_x<<<dim3(2048, 1, 2), 256>>>(x_cls, x_reg);
    w_prep<<<3072 + 2048, 256>>>(W_cls, W_reg);

    // 2) qkv projections (cls v-columns also write x_ori -> out[:,1024:2048])
    hm_gemm_k<2><<<1280, 256, DS1>>>(out);

    // 3) normalize q/k/v + Vt transpose, merged into one launch
    norm_vt<<<10240 + 2048, 256>>>();

    // 4) scores (16 planes) + single-segment symmetric vv (bf16 out), vv LPT-first
    hm_gemm_k<3><<<4232, 256, DS2>>>(nullptr);

    // 5) fused softmax + sim (reads S*, writes P bf16 hi|lo + sim output)
    row_fuse<<<NTOK, 256>>>(cls_score, fg_score, out + (size_t)NTOK * NTOK);

    // 6) x = P @ V split-K partials (reuse g_Scls), then reduce -> out[:,0:1024]
    hm_gemm_k<1><<<768, 256, DS1>>>(nullptr);
    pv_finish<<<(NTOK * 1024 / 4) / 256, 256>>>(Scls, out);
}

// round 16
// speedup vs baseline: 1.6325x; 1.0217x over previous
#include <cuda_runtime.h>
#include <cuda_bf16.h>
#include <cuda_fp16.h>
#include <cstdint>
#include <cstddef>

typedef __nv_bfloat16 bf16;
#define NTOK 2048
#define HEADS 8
#define STAGES 3

// ---------------- scratch (static device globals) ----------------
__device__ float g_qkv_cls[(size_t)NTOK * 3072];
__device__ float g_qk_reg [(size_t)NTOK * 2048];
__device__ bf16  g_Xc[(size_t)NTOK * 2048];
__device__ bf16  g_Xr[(size_t)NTOK * 2048];
__device__ bf16  g_Wc[(size_t)3072 * 2048];
__device__ bf16  g_Wr[(size_t)2048 * 2048];
__device__ bf16  g_qc[(size_t)HEADS * NTOK * 256];
__device__ bf16  g_kc[(size_t)HEADS * NTOK * 256];
__device__ bf16  g_qr[(size_t)HEADS * NTOK * 256];
__device__ bf16  g_kr[(size_t)HEADS * NTOK * 256];
__device__ bf16  g_vn[(size_t)NTOK * 2048];             // [n][h*128+d] hi only
__device__ bf16  g_Vt[(size_t)HEADS * 128 * 4096];
__device__ __half g_Scls[(size_t)HEADS * NTOK * NTOK];  // fp16 scores; reused (cast) for PV partials
__device__ __half g_Sreg[(size_t)HEADS * NTOK * NTOK];
__device__ bf16  g_Svv [(size_t)NTOK * NTOK];           // head-sum vn.vn^T, bf16 (mask only)
__device__ bf16  g_P[(size_t)HEADS * NTOK * 4096];

// ---------------- helpers ----------------
__device__ __forceinline__ uint32_t s2u(const void* p) {
    uint32_t a;
    asm("{ .reg .u64 t; cvta.to.shared.u64 t, %1; cvt.u32.u64 %0, t; }" : "=r"(a) : "l"(p));
    return a;
}
#define SWZ(x) ((x) ^ (((x) >> 3) & 0x70))

__device__ __forceinline__ void cpasync16(uint32_t s, const void* g) {
    asm volatile("cp.async.cg.shared.global [%0], [%1], 16;" :: "r"(s), "l"(g) : "memory");
}
#define CP_COMMIT() asm volatile("cp.async.commit_group;" ::: "memory")
#define CP_WAIT(n)  asm volatile("cp.async.wait_group %0;" :: "n"(n) : "memory")

__device__ __forceinline__ void ldsm4(uint32_t& r0, uint32_t& r1, uint32_t& r2, uint32_t& r3, uint32_t a) {
    asm volatile("ldmatrix.sync.aligned.m8n8.x4.shared.b16 {%0,%1,%2,%3}, [%4];"
                 : "=r"(r0), "=r"(r1), "=r"(r2), "=r"(r3) : "r"(a));
}
__device__ __forceinline__ void mma16816(float* d, const uint32_t* a, uint32_t b0, uint32_t b1) {
    asm volatile(
        "mma.sync.aligned.m16n8k16.row.col.f32.bf16.bf16.f32 "
        "{%0,%1,%2,%3}, {%4,%5,%6,%7}, {%8,%9}, {%0,%1,%2,%3};"
        : "+f"(d[0]), "+f"(d[1]), "+f"(d[2]), "+f"(d[3])
        : "r"(a[0]), "r"(a[1]), "r"(a[2]), "r"(a[3]), "r"(b0), "r"(b1));
}

// ---------------- HMMA NT GEMM, per-mode tile selection ----------------
// MODE 1: PV split-K  MW=1 (64x128, 3 CTA/SM)  grid 768:  fp32 partials into (float*)g_Scls
// MODE 2: qkv merged  MW=1 (64x128, 3 CTA/SM)  grid 1280: x<768 cls tile (v-columns
//                     j0>=2048 ALSO write x_ori -> xout[:,1024:2048]), else reg tile
// MODE 3: scores+vv   MW=2 (128x128, 2 CTA/SM) grid 4232: x<136 vv symm tile FIRST (bf16
//                     out, single-seg); score tiles write fp16.
template<int MODE>
__global__ __launch_bounds__(256, (MODE == 3) ? 2 : 3) void hm_gemm_k(float* __restrict__ xout)
{
    extern __shared__ char dsm[];
    constexpr int MW = (MODE == 3) ? 2 : 1;
    constexpr int NT = 2 * MW;                     // n-tiles (of 8) per warp
    constexpr int NP = NT / 2;                     // b ldsm.x4 per warp
    constexpr int MROWS = MW * 64;
    constexpr uint32_t ABYTES = (uint32_t)MROWS * 128u;
    constexpr uint32_t STGB = ABYTES + 16384u;
    const size_t QH = (size_t)NTOK * 256, SH = (size_t)NTOK * NTOK;

    const bf16 *A, *B; float* C = nullptr; __half* Ch = nullptr;
    int lda, ldb, ldc, K, i0, j0;
    bool symm = false; int bi = 0, bj = 0;
    bool vcols = false;

    if (MODE == 2) {
        K = 1024; lda = 2048; ldb = 2048;
        const int t = blockIdx.x;
        if (t < 768) {
            A = g_Xc; B = g_Wc; C = g_qkv_cls; ldc = 3072;
            i0 = (t / 24) * 64;  j0 = (t % 24) * 128;
            vcols = (j0 >= 2048);
        } else {
            const int t2 = t - 768;
            A = g_Xr; B = g_Wr; C = g_qk_reg; ldc = 2048;
            i0 = (t2 >> 4) * 64;  j0 = (t2 & 15) * 128;
        }
    } else if (MODE == 3) {
        const int x = blockIdx.x;
        if (x < 136) {                 // vv long tiles first (LPT); single segment
            symm = true;
            bi = (int)((33.0f - sqrtf(fmaxf(0.0f, 1089.0f - 8.0f * (float)x))) * 0.5f);
            while ((bi + 1) * (33 - (bi + 1)) / 2 <= x) bi++;
            while (bi * (33 - bi) / 2 > x) bi--;
            bj = bi + (x - bi * (33 - bi) / 2);
            i0 = bi * 128; j0 = bj * 128;
            A = g_vn; B = g_vn; lda = 2048; ldb = 2048; ldc = 2048; K = 1024;
        } else {
            const int t = x - 136;
            const int z = t >> 8, r = t & 255;
            K = 128; lda = 256; ldb = 256; ldc = 2048;
            if (z < 8) { A = g_qc + z * QH;       B = g_kc + z * QH;       Ch = g_Scls + z * SH; }
            else       { A = g_qr + (z - 8) * QH; B = g_kr + (z - 8) * QH; Ch = g_Sreg + (z - 8) * SH; }
            i0 = (r >> 4) * 128;  j0 = (r & 15) * 128;
        }
    } else {  // MODE 1: PV
        const int z = blockIdx.x >> 5, yt = blockIdx.x & 31;
        const int head = z / 3, seg = z % 3;
        K = 2048;
        A = g_P  + (size_t)head * NTOK * 4096 + ((seg == 1) ? (size_t)K : 0);
        B = g_Vt + (size_t)head * 128  * 4096 + ((seg == 2) ? (size_t)K : 0);
        C = (float*)g_Scls + (size_t)z * NTOK * 128;
        lda = 4096; ldb = 4096; ldc = 128;
        i0 = yt * 64; j0 = 0;
    }

    const int nkc = K >> 6;
    const int NC  = (MODE == 1) ? nkc : ((MODE == 3 && symm) ? nkc : 3 * nkc);
    const int tid = threadIdx.x;
    const uint32_t stage0 = (s2u(dsm) + 1023u) & ~1023u;

    const int lane = tid & 31, wid = tid >> 5;
    const int wm = wid % MW, wn = wid / MW;
    const int lt = lane >> 3, lr = lane & 7;
    const int arow = wm * 64 + (lt & 1) * 8 + lr;
    const int brow = wn * (NT * 8) + (lt & 1) * 8 + lr;
    const int kbsub = (lt >> 1) * 16;
    const uint32_t xm = (uint32_t)(lr << 4);

    float acc[4][NT][4];
#pragma unroll
    for (int i = 0; i < 4; i++)
#pragma unroll
        for (int j = 0; j < NT; j++)
#pragma unroll
            for (int q = 0; q < 4; q++) acc[i][j][q] = 0.0f;

    auto fill = [&](int s, int c) {
        const bf16 *Ab, *Bb;
        if (MODE == 1) {                               // compile-time single-seg
            const int kk = c << 6;
            Ab = A + kk;  Bb = B + kk;
        } else if (MODE == 3 && symm) {
            const int kk = c << 6;
            Ab = A + kk;  Bb = B + kk;
        } else {
            const int seg = c / nkc, kk = (c - seg * nkc) << 6;
            Ab = A + ((seg == 1) ? K : 0) + kk;
            Bb = B + ((seg == 2) ? K : 0) + kk;
        }
        const uint32_t sA = stage0 + (uint32_t)s * STGB, sB = sA + ABYTES;
#pragma unroll
        for (int i = 0; i < 2 * MW; i++) {
            const int id = (i << 8) + tid;
            const int row = id >> 3, c16 = id & 7;
            const uint32_t so = SWZ((uint32_t)((row << 7) + (c16 << 4)));
            cpasync16(sA + so, Ab + (size_t)(i0 + row) * lda + (c16 << 3));
        }
#pragma unroll
        for (int i = 0; i < 4; i++) {
            const int id = (i << 8) + tid;
            const int row = id >> 3, c16 = id & 7;
            const uint32_t so = SWZ((uint32_t)((row << 7) + (c16 << 4)));
            cpasync16(sB + so, Bb + (size_t)(j0 + row) * ldb + (c16 << 3));
        }
    };

#pragma unroll
    for (int c = 0; c < STAGES; c++) { fill(c, c); CP_COMMIT(); }

    for (int c = 0; c < NC; ++c) {
        const int s = c - (c / STAGES) * STAGES;
        CP_WAIT(1);
        __syncthreads();
        if (c >= 1) {
            const int cn = c + 2;
            if (cn < NC) fill(cn - (cn / STAGES) * STAGES, cn);
            CP_COMMIT();
        }
        const uint32_t sA = stage0 + (uint32_t)s * STGB, sB = sA + ABYTES;
#pragma unroll
        for (int ks = 0; ks < 4; ks++) {
            const uint32_t koff = ((uint32_t)(ks * 32 + kbsub)) ^ xm;
            uint32_t a[4][4], b[NP][4];
#pragma unroll
            for (int mt = 0; mt < 4; mt++)
                ldsm4(a[mt][0], a[mt][1], a[mt][2], a[mt][3],
                      sA + (uint32_t)((arow + mt * 16) << 7) + koff);
#pragma unroll
            for (int np = 0; np < NP; np++)
                ldsm4(b[np][0], b[np][1], b[np][2], b[np][3],
                      sB + (uint32_t)((brow + np * 16) << 7) + koff);
#pragma unroll
            for (int mt = 0; mt < 4; mt++)
#pragma unroll
                for (int nt = 0; nt < NT; nt++)
                    mma16816(acc[mt][nt], a[mt], b[nt >> 1][nt & 1], b[nt >> 1][(nt & 1) + 2]);
        }
    }

    const int rq = lane >> 2, cq = (lane & 3) * 2;
    if (MODE == 3) {
        if (symm) {
            // vv: bf16 output (mask-only consumer)
#pragma unroll
            for (int mt = 0; mt < 4; mt++) {
                const int row = i0 + wm * 64 + mt * 16 + rq;
#pragma unroll
                for (int nt = 0; nt < NT; nt++) {
                    const int col = j0 + wn * (NT * 8) + nt * 8 + cq;
                    *(__nv_bfloat162*)(g_Svv + (size_t)row * 2048 + col) =
                        __nv_bfloat162(__float2bfloat16(acc[mt][nt][0]), __float2bfloat16(acc[mt][nt][1]));
                    *(__nv_bfloat162*)(g_Svv + (size_t)(row + 8) * 2048 + col) =
                        __nv_bfloat162(__float2bfloat16(acc[mt][nt][2]), __float2bfloat16(acc[mt][nt][3]));
                }
            }
            if (bi != bj) {   // mirror via padded smem transpose
                float* smf = (float*)dsm;
                __syncthreads();
#pragma unroll
                for (int mt = 0; mt < 4; mt++) {
                    const int r = wm * 64 + mt * 16 + rq;
#pragma unroll
                    for (int nt = 0; nt < NT; nt++) {
                        const int cc = wn * (NT * 8) + nt * 8 + cq;
                        smf[r * 133 + cc]           = acc[mt][nt][0];
                        smf[r * 133 + cc + 1]       = acc[mt][nt][1];
                        smf[(r + 8) * 133 + cc]     = acc[mt][nt][2];
                        smf[(r + 8) * 133 + cc + 1] = acc[mt][nt][3];
                    }
                }
                __syncthreads();
                const int r2 = tid & 127;
                const int c2b = (tid >> 7) * 64;
                bf16* Crow = g_Svv + (size_t)(j0 + r2) * 2048 + i0 + c2b;
#pragma unroll
                for (int q = 0; q < 16; q++) {
                    union { __nv_bfloat162 h2[2]; uint2 u; } p;
                    p.h2[0] = __nv_bfloat162(__float2bfloat16(smf[(c2b + 4 * q + 0) * 133 + r2]),
                                             __float2bfloat16(smf[(c2b + 4 * q + 1) * 133 + r2]));
                    p.h2[1] = __nv_bfloat162(__float2bfloat16(smf[(c2b + 4 * q + 2) * 133 + r2]),
                                             __float2bfloat16(smf[(c2b + 4 * q + 3) * 133 + r2]));
                    *(uint2*)(Crow + 4 * q) = p.u;
                }
            }
        } else {
            // scores: fp16 output (exp consumer; 2^-12 rel err -> ~1e-4 out err)
#pragma unroll
            for (int mt = 0; mt < 4; mt++) {
                const int row = i0 + wm * 64 + mt * 16 + rq;
#pragma unroll
                for (int nt = 0; nt < NT; nt++) {
                    const int col = j0 + wn * (NT * 8) + nt * 8 + cq;
                    *(__half2*)(Ch + (size_t)row * ldc + col) =
                        __floats2half2_rn(acc[mt][nt][0], acc[mt][nt][1]);
                    *(__half2*)(Ch + (size_t)(row + 8) * ldc + col) =
                        __floats2half2_rn(acc[mt][nt][2], acc[mt][nt][3]);
                }
            }
        }
    } else {
#pragma unroll
        for (int mt = 0; mt < 4; mt++) {
            const int row = i0 + wm * 64 + mt * 16 + rq;
#pragma unroll
            for (int nt = 0; nt < NT; nt++) {
                const int col = j0 + wn * (NT * 8) + nt * 8 + cq;
                const float2 v0 = make_float2(acc[mt][nt][0], acc[mt][nt][1]);
                const float2 v1 = make_float2(acc[mt][nt][2], acc[mt][nt][3]);
                *(float2*)(C + (size_t)row * ldc + col)       = v0;
                *(float2*)(C + (size_t)(row + 8) * ldc + col) = v1;
                if (MODE == 2 && vcols) {   // x_ori: out[:,1024:2048] = v-block
                    *(float2*)(xout + (size_t)row * 2048 + col - 1024)       = v0;
                    *(float2*)(xout + (size_t)(row + 8) * 2048 + col - 1024) = v1;
                }
            }
        }
    }
}

// ---------------- PV split-K reduce ----------------
__global__ __launch_bounds__(256) void pv_finish(const float* __restrict__ part, float* __restrict__ out)
{
    const size_t t = (size_t)blockIdx.x * 256 + threadIdx.x;   // over 2048*1024/4
    const size_t e = t * 4;
    const int n = (int)(e >> 10), c = (int)(e & 1023);
    const int h = c >> 7, d = c & 127;
    const size_t base = (((size_t)h * 3 * NTOK) + n) * 128 + d;
    const size_t sg = (size_t)NTOK * 128;
    float4 v0 = *(const float4*)(part + base);
    float4 v1 = *(const float4*)(part + base + sg);
    float4 v2 = *(const float4*)(part + base + 2 * sg);
    *(float4*)(out + (size_t)n * 2048 + c) =
        make_float4(v0.x + v1.x + v2.x, v0.y + v1.y + v2.y,
                    v0.z + v1.z + v2.z, v0.w + v1.w + v2.w);
}

// ---------------- fp32 -> bf16 hi|lo split, float4-vectorized ----------------
__global__ __launch_bounds__(256) void split_x(const float* __restrict__ xc, const float* __restrict__ xr)
{
    const size_t i = ((size_t)blockIdx.x * 256 + threadIdx.x) * 4;
    const int n = (int)(i >> 10), c = (int)(i & 1023);
    const float4 v = *(const float4*)((blockIdx.z == 0 ? xc : xr) + i);
    bf16* o = (blockIdx.z == 0 ? g_Xc : g_Xr) + (size_t)n * 2048 + c;
    const float a[4] = { v.x, v.y, v.z, v.w };
    union { __nv_bfloat162 h2[2]; uint2 u; } ph, pl;
#pragma unroll
    for (int j = 0; j < 2; j++) {
        const bf16 h0 = __float2bfloat16(a[2 * j]);
        const bf16 h1 = __float2bfloat16(a[2 * j + 1]);
        ph.h2[j] = __nv_bfloat162(h0, h1);
        pl.h2[j] = __nv_bfloat162(
            __float2bfloat16(a[2 * j]     - __bfloat162float(h0)),
            __float2bfloat16(a[2 * j + 1] - __bfloat162float(h1)));
    }
    *(uint2*)(o)        = ph.u;
    *(uint2*)(o + 1024) = pl.u;
}

// ---------------- transpose+split body ----------------
__device__ __forceinline__ void tsplit_body(
    const float* __restrict__ in, bf16* __restrict__ out,
    int R, int ldin, int ldout, int r0, int c0)
{
    __shared__ float t[32][33];
    const int tx = threadIdx.x & 31, ty = threadIdx.x >> 5;
#pragma unroll
    for (int i = 0; i < 4; i++)
        t[ty + i * 8][tx] = in[(size_t)(r0 + ty + i * 8) * ldin + c0 + tx];
    __syncthreads();
#pragma unroll
    for (int i = 0; i < 4; i++) {
        const int cc = ty + i * 8;
        const float v = t[tx][cc];
        const bf16 h = __float2bfloat16(v);
        out[(size_t)(c0 + cc) * ldout + r0 + tx]     = h;
        out[(size_t)(c0 + cc) * ldout + R + r0 + tx] = __float2bfloat16(v - __bfloat162float(h));
    }
}

__global__ __launch_bounds__(256) void w_prep(
    const float* __restrict__ Wcls, const float* __restrict__ Wreg)
{
    const int x = blockIdx.x;
    if (x < 3072) {
        tsplit_body(Wcls, g_Wc, 1024, 3072, 2048, (x / 96) * 32, (x % 96) * 32);
    } else {
        const int t2 = x - 3072;
        tsplit_body(Wreg, g_Wr, 1024, 3072, 2048, (t2 / 64) * 32, (t2 % 64) * 32);
    }
}

// ---------------- merged: L2-normalize+split (x<10240) OR Vt transpose tile ----------
__global__ __launch_bounds__(256) void norm_vt()
{
    if (blockIdx.x < 10240) {
        const int gid  = blockIdx.x * 8 + (threadIdx.x >> 5);
        const int lane = threadIdx.x & 31;
        const int op  = gid / (NTOK * HEADS);
        const int rem = gid - op * (NTOK * HEADS);
        const int n = rem >> 3, h = rem & 7;

        const float* src; bf16* dst; int lo_off;
        if (op == 0)      { src = g_qkv_cls + (size_t)n * 3072 + h * 128;        dst = g_qc + ((size_t)h * NTOK + n) * 256; lo_off = 128; }
        else if (op == 1) { src = g_qkv_cls + (size_t)n * 3072 + 1024 + h * 128; dst = g_kc + ((size_t)h * NTOK + n) * 256; lo_off = 128; }
        else if (op == 2) { src = g_qk_reg  + (size_t)n * 2048 + h * 128;        dst = g_qr + ((size_t)h * NTOK + n) * 256; lo_off = 128; }
        else if (op == 3) { src = g_qk_reg  + (size_t)n * 2048 + 1024 + h * 128; dst = g_kr + ((size_t)h * NTOK + n) * 256; lo_off = 128; }
        else              { src = g_qkv_cls + (size_t)n * 3072 + 2048 + h * 128; dst = g_vn + (size_t)n * 2048 + h * 128;   lo_off = 0; }

        float4 v = *(const float4*)(src + lane * 4);
        float ss = v.x * v.x + v.y * v.y + v.z * v.z + v.w * v.w;
#pragma unroll
        for (int o = 16; o; o >>= 1) ss += __shfl_xor_sync(0xffffffffu, ss, o);
        const float r = 1.0f / sqrtf(ss);
        float a[4] = { v.x * r, v.y * r, v.z * r, v.w * r };
#pragma unroll
        for (int j = 0; j < 4; j++) {
            const bf16 h2 = __float2bfloat16(a[j]);
            dst[lane * 4 + j] = h2;
            if (lo_off)
                dst[lo_off + lane * 4 + j] = __float2bfloat16(a[j] - __bfloat162float(h2));
        }
    } else {
        const int t2 = (int)blockIdx.x - 10240;
        const int bz = t2 >> 8, rem = t2 & 255;
        const int by = rem >> 2, bx = rem & 3;
        tsplit_body(g_qkv_cls + 2048 + bz * 128, g_Vt + (size_t)bz * 128 * 4096,
                    2048, 3072, 4096, by * 32, bx * 32);
    }
}

// ---------------- FMA-only exp + block reductions ----------------
__device__ __forceinline__ float fast_exp(float x)
{
    float t = x * 1.4426950408889634f;
    t = fmaxf(t, -120.0f);
    float r = t + 12582912.0f;
    float f = t - (r - 12582912.0f);
    int   k = __float_as_int(r) - 0x4B400000;
    float p = 1.5403530393381609e-4f;
    p = fmaf(p, f, 1.3333558146428443e-3f);
    p = fmaf(p, f, 9.618129107628477e-3f);
    p = fmaf(p, f, 5.550410866482158e-2f);
    p = fmaf(p, f, 2.402265069591007e-1f);
    p = fmaf(p, f, 6.931471805599453e-1f);
    p = fmaf(p, f, 1.0f);
    return p * __int_as_float((k + 127) << 23);
}
__device__ __forceinline__ float block_max(float v, float* red)
{
#pragma unroll
    for (int o = 16; o; o >>= 1) v = fmaxf(v, __shfl_xor_sync(0xffffffffu, v, o));
    if ((threadIdx.x & 31) == 0) red[threadIdx.x >> 5] = v;
    __syncthreads();
    float r = red[0];
#pragma unroll
    for (int i = 1; i < 8; i++) r = fmaxf(r, red[i]);
    __syncthreads();
    return r;
}
__device__ __forceinline__ float block_sum(float v, float* red)
{
#pragma unroll
    for (int o = 16; o; o >>= 1) v += __shfl_xor_sync(0xffffffffu, v, o);
    if ((threadIdx.x & 31) == 0) red[threadIdx.x >> 5] = v;
    __syncthreads();
    float r = red[0];
#pragma unroll
    for (int i = 1; i < 8; i++) r += red[i];
    __syncthreads();
    return r;
}
__device__ __forceinline__ void block_sum2(float& a, float& b, float* red2)
{
#pragma unroll
    for (int o = 16; o; o >>= 1) {
        a += __shfl_xor_sync(0xffffffffu, a, o);
        b += __shfl_xor_sync(0xffffffffu, b, o);
    }
    if ((threadIdx.x & 31) == 0) {
        red2[(threadIdx.x >> 5) * 2]     = a;
        red2[(threadIdx.x >> 5) * 2 + 1] = b;
    }
    __syncthreads();
    float ra = red2[0], rb = red2[1];
#pragma unroll
    for (int i = 1; i < 8; i++) { ra += red2[i * 2]; rb += red2[i * 2 + 1]; }
    __syncthreads();
    a = ra; b = rb;
}

// ---------------- fused masked dual softmax + combine + sim_round2 -----------------
__global__ __launch_bounds__(256) void row_fuse(
    const float* __restrict__ cls_score, const float* __restrict__ fg_score,
    float* __restrict__ out_sim)
{
    const int n = blockIdx.x;
    const int tid = threadIdx.x;
    const int m0 = tid * 8;
    __shared__ float s_sc[NTOK];
    __shared__ float red[16];

    float fc[8], fr[8];
    float lsc = -1e30f, lfs = -1e30f;
#pragma unroll
    for (int j = 0; j < 8; j++) {
        const int m = m0 + j;
        const float a = cls_score[m], b = fg_score[m];
        fc[j] = a;  fr[j] = b;
        s_sc[m] = a;
        lsc = fmaxf(lsc, a);  lfs = fmaxf(lfs, b);
    }
    __syncthreads();
    const float Mc = 25.0f * block_max(lsc, red) + 1.0f;
    const float Mr = 25.0f * block_max(lfs, red) + 1.0f;
    const float cthr = s_sc[n] - 0.1f;
    const float fthr = fg_score[n] - 0.1f;
#pragma unroll
    for (int j = 0; j < 8; j++) {
        fc[j] = (fc[j] > cthr) ? 25.0f * fc[j] : 0.0f;
        fr[j] = (fr[j] > fthr) ? 25.0f * fr[j] : 0.0f;
    }

    float vvacc[8];
    {
        const uint4 u = *(const uint4*)(g_Svv + (size_t)n * NTOK + m0);
        const __nv_bfloat162* hv = (const __nv_bfloat162*)&u;
#pragma unroll
        for (int j = 0; j < 4; j++) {
            vvacc[2 * j]     = __bfloat162float(hv[j].x);
            vvacc[2 * j + 1] = __bfloat162float(hv[j].y);
        }
    }

    float simacc[8];
#pragma unroll
    for (int j = 0; j < 8; j++) simacc[j] = 0.0f;

    for (int h = 0; h < HEADS; h++) {
        const size_t base = ((size_t)h * NTOK + n) * NTOK + m0;
        bf16* Pb = g_P + ((size_t)h * NTOK + n) * 4096 + m0;
        float ec[8], er[8], sv[8];

        {
            const uint4 u = *(const uint4*)(g_Scls + base);   // 8 fp16
            const __half2* hp = (const __half2*)&u;
#pragma unroll
            for (int j = 0; j < 4; j++) {
                const float2 f = __half22float2(hp[j]);
                sv[2 * j] = f.x;  sv[2 * j + 1] = f.y;
            }
        }
        float smc = 0.0f;
#pragma unroll
        for (int j = 0; j < 8; j++) { ec[j] = fast_exp(sv[j] * fc[j] - Mc); smc += ec[j]; }

        {
            const uint4 u = *(const uint4*)(g_Sreg + base);
            const __half2* hp = (const __half2*)&u;
#pragma unroll
            for (int j = 0; j < 4; j++) {
                const float2 f = __half22float2(hp[j]);
                sv[2 * j] = f.x;  sv[2 * j + 1] = f.y;
            }
        }
        float smr = 0.0f;
#pragma unroll
        for (int j = 0; j < 8; j++) { er[j] = fast_exp(sv[j] * fr[j] - Mr); smr += er[j]; }

        block_sum2(smc, smr, red);
        const float ic = 0.5f / smc, ir = 0.5f / smr;

        float pv[8];
#pragma unroll
        for (int j = 0; j < 8; j++) pv[j] = ec[j] * ic + er[j] * ir;

        union { __nv_bfloat162 h2[4]; uint4 u; } ph, pl;
#pragma unroll
        for (int j = 0; j < 4; j++) {
            const bf16 h0 = __float2bfloat16(pv[2 * j]);
            const bf16 h1 = __float2bfloat16(pv[2 * j + 1]);
            ph.h2[j] = __nv_bfloat162(h0, h1);
            pl.h2[j] = __nv_bfloat162(
                __float2bfloat16(pv[2 * j]     - __bfloat162float(h0)),
                __float2bfloat16(pv[2 * j + 1] - __bfloat162float(h1)));
        }
        *(uint4*)(Pb)        = ph.u;
        *(uint4*)(Pb + 2048) = pl.u;

#pragma unroll
        for (int j = 0; j < 8; j++) simacc[j] += pv[j];
    }

    float sm = 0.0f;
#pragma unroll
    for (int j = 0; j < 8; j++) { simacc[j] = fast_exp(simacc[j] * 0.125f - 1.0f); sm += simacc[j]; }
    sm = block_sum(sm, red);
    float msum = 0.0f;
#pragma unroll
    for (int j = 0; j < 8; j++) {
        const float soft = simacc[j] / sm;
        const float keep = (vvacc[j] > 6.0f) ? soft : 0.0f;
        simacc[j] = keep; msum += keep;
    }
    msum = block_sum(msum, red);
    const float rn = 1.0f / msum;
    float4 o0 = make_float4(simacc[0] * rn, simacc[1] * rn, simacc[2] * rn, simacc[3] * rn);
    float4 o1 = make_float4(simacc[4] * rn, simacc[5] * rn, simacc[6] * rn, simacc[7] * rn);
    *(float4*)(out_sim + (size_t)n * NTOK + m0)     = o0;
    *(float4*)(out_sim + (size_t)n * NTOK + m0 + 4) = o1;
}

// -------------------------------- launch ----------------------------------------
extern "C" void kernel_launch(void* const* d_in, const int* in_sizes, int n_in,
                              void* d_out, int out_size)
{
    (void)in_sizes; (void)n_in; (void)out_size;
    const float* x_cls     = (const float*)d_in[0];
    const float* x_reg     = (const float*)d_in[1];
    const float* cls_score = (const float*)d_in[2];
    const float* fg_score  = (const float*)d_in[3];
    const float* W_cls     = (const float*)d_in[4];
    const float* W_reg     = (const float*)d_in[5];
    float* out = (float*)d_out;

    void* Scls;
    cudaGetSymbolAddress(&Scls, g_Scls);

    const int DS1 = STAGES * 24576 + 1024;   // MW=1 stages (64x128), 3 CTAs/SM
    const int DS2 = STAGES * 32768 + 1024;   // MW=2 stages (128x128), 2 CTAs/SM
    cudaFuncSetAttribute((const void*)hm_gemm_k<1>, cudaFuncAttributeMaxDynamicSharedMemorySize, DS1);
    cudaFuncSetAttribute((const void*)hm_gemm_k<2>, cudaFuncAttributeMaxDynamicSharedMemorySize, DS1);
    cudaFuncSetAttribute((const void*)hm_gemm_k<3>, cudaFuncAttributeMaxDynamicSharedMemorySize, DS2);

    // 1) split inputs (vectorized); merged W transpose/split
    split_x<<<dim3(2048, 1, 2), 256>>>(x_cls, x_reg);
    w_prep<<<3072 + 2048, 256>>>(W_cls, W_reg);

    // 2) qkv projections (cls v-columns also write x_ori -> out[:,1024:2048])
    hm_gemm_k<2><<<1280, 256, DS1>>>(out);

    // 3) normalize q/k/v + Vt transpose, merged into one launch
    norm_vt<<<10240 + 2048, 256>>>();

    // 4) scores (fp16 out, 16 planes) + single-segment symmetric vv (bf16 out)
    hm_gemm_k<3><<<4232, 256, DS2>>>(nullptr);

    // 5) fused softmax + sim (reads fp16 S*, writes P bf16 hi|lo + sim output)
    row_fuse<<<NTOK, 256>>>(cls_score, fg_score, out + (size_t)NTOK * NTOK);

    // 6) x = P @ V split-K partials (reuse g_Scls as fp32), then reduce -> out[:,0:1024]
    hm_gemm_k<1><<<768, 256, DS1>>>(nullptr);
    pv_finish<<<(NTOK * 1024 / 4) / 256, 256>>>((const float*)Scls, out);
}

// round 17
// speedup vs baseline: 1.8359x; 1.1246x over previous
#include <cuda_runtime.h>
#include <cuda_bf16.h>
#include <cuda_fp16.h>
#include <cstdint>
#include <cstddef>

typedef __nv_bfloat16 bf16;
#define NTOK 2048
#define HEADS 8
#define STAGES 3

// ---------------- scratch (static device globals) ----------------
__device__ float g_qkv_cls[(size_t)NTOK * 3072];
__device__ float g_qk_reg [(size_t)NTOK * 2048];
__device__ bf16  g_Xc[(size_t)NTOK * 2048];
__device__ bf16  g_Xr[(size_t)NTOK * 2048];
__device__ bf16  g_Wc[(size_t)3072 * 2048];
__device__ bf16  g_Wr[(size_t)2048 * 2048];
__device__ bf16  g_qc[(size_t)HEADS * NTOK * 256];
__device__ bf16  g_kc[(size_t)HEADS * NTOK * 256];
__device__ bf16  g_qr[(size_t)HEADS * NTOK * 256];
__device__ bf16  g_kr[(size_t)HEADS * NTOK * 256];
__device__ bf16  g_vn[(size_t)NTOK * 2048];             // [n][h*128+d] hi only
__device__ __half g_Vt[(size_t)HEADS * 128 * 2048];     // fp16, single copy
__device__ __half g_Scls[(size_t)HEADS * NTOK * NTOK];  // fp16 scores
__device__ __half g_Sreg[(size_t)HEADS * NTOK * NTOK];
__device__ bf16  g_Svv [(size_t)NTOK * NTOK];           // head-sum vn.vn^T, bf16 (mask only)
__device__ __half g_P[(size_t)HEADS * NTOK * 2048];     // fp16 attention weights

// ---------------- helpers ----------------
__device__ __forceinline__ uint32_t s2u(const void* p) {
    uint32_t a;
    asm("{ .reg .u64 t; cvta.to.shared.u64 t, %1; cvt.u32.u64 %0, t; }" : "=r"(a) : "l"(p));
    return a;
}
#define SWZ(x) ((x) ^ (((x) >> 3) & 0x70))

__device__ __forceinline__ void cpasync16(uint32_t s, const void* g) {
    asm volatile("cp.async.cg.shared.global [%0], [%1], 16;" :: "r"(s), "l"(g) : "memory");
}
#define CP_COMMIT() asm volatile("cp.async.commit_group;" ::: "memory")
#define CP_WAIT(n)  asm volatile("cp.async.wait_group %0;" :: "n"(n) : "memory")

__device__ __forceinline__ void ldsm4(uint32_t& r0, uint32_t& r1, uint32_t& r2, uint32_t& r3, uint32_t a) {
    asm volatile("ldmatrix.sync.aligned.m8n8.x4.shared.b16 {%0,%1,%2,%3}, [%4];"
                 : "=r"(r0), "=r"(r1), "=r"(r2), "=r"(r3) : "r"(a));
}
__device__ __forceinline__ void mma16816(float* d, const uint32_t* a, uint32_t b0, uint32_t b1) {
    asm volatile(
        "mma.sync.aligned.m16n8k16.row.col.f32.bf16.bf16.f32 "
        "{%0,%1,%2,%3}, {%4,%5,%6,%7}, {%8,%9}, {%0,%1,%2,%3};"
        : "+f"(d[0]), "+f"(d[1]), "+f"(d[2]), "+f"(d[3])
        : "r"(a[0]), "r"(a[1]), "r"(a[2]), "r"(a[3]), "r"(b0), "r"(b1));
}
__device__ __forceinline__ void mma16816h(float* d, const uint32_t* a, uint32_t b0, uint32_t b1) {
    asm volatile(
        "mma.sync.aligned.m16n8k16.row.col.f32.f16.f16.f32 "
        "{%0,%1,%2,%3}, {%4,%5,%6,%7}, {%8,%9}, {%0,%1,%2,%3};"
        : "+f"(d[0]), "+f"(d[1]), "+f"(d[2]), "+f"(d[3])
        : "r"(a[0]), "r"(a[1]), "r"(a[2]), "r"(a[3]), "r"(b0), "r"(b1));
}

// ---------------- HMMA NT GEMM, per-mode tile selection ----------------
// MODE 1: PV fp16 single-seg  MW=1, grid 256 (ONE wave): head=x>>5, yt=x&31.
//         C = out[:, head*128 : head*128+128] directly (no reduce kernel).
// MODE 2: qkv merged  MW=1, grid 1280: x<768 cls tile (v-cols j0>=2048 also write x_ori)
// MODE 3: scores+vv   MW=2, grid 4232: x<136 vv symm tile FIRST (bf16 out, single-seg);
//         score tiles write fp16.
template<int MODE>
__global__ __launch_bounds__(256, (MODE == 3) ? 2 : 3) void hm_gemm_k(float* __restrict__ xout)
{
    extern __shared__ char dsm[];
    constexpr int MW = (MODE == 3) ? 2 : 1;
    constexpr int NT = 2 * MW;                     // n-tiles (of 8) per warp
    constexpr int NP = NT / 2;                     // b ldsm.x4 per warp
    constexpr int MROWS = MW * 64;
    constexpr uint32_t ABYTES = (uint32_t)MROWS * 128u;
    constexpr uint32_t STGB = ABYTES + 16384u;
    const size_t QH = (size_t)NTOK * 256, SH = (size_t)NTOK * NTOK;

    const bf16 *A, *B; float* C = nullptr; __half* Ch = nullptr;
    int lda, ldb, ldc, K, i0, j0;
    bool symm = false; int bi = 0, bj = 0;
    bool vcols = false;

    if (MODE == 2) {
        K = 1024; lda = 2048; ldb = 2048;
        const int t = blockIdx.x;
        if (t < 768) {
            A = g_Xc; B = g_Wc; C = g_qkv_cls; ldc = 3072;
            i0 = (t / 24) * 64;  j0 = (t % 24) * 128;
            vcols = (j0 >= 2048);
        } else {
            const int t2 = t - 768;
            A = g_Xr; B = g_Wr; C = g_qk_reg; ldc = 2048;
            i0 = (t2 >> 4) * 64;  j0 = (t2 & 15) * 128;
        }
    } else if (MODE == 3) {
        const int x = blockIdx.x;
        if (x < 136) {
            symm = true;
            bi = (int)((33.0f - sqrtf(fmaxf(0.0f, 1089.0f - 8.0f * (float)x))) * 0.5f);
            while ((bi + 1) * (33 - (bi + 1)) / 2 <= x) bi++;
            while (bi * (33 - bi) / 2 > x) bi--;
            bj = bi + (x - bi * (33 - bi) / 2);
            i0 = bi * 128; j0 = bj * 128;
            A = g_vn; B = g_vn; lda = 2048; ldb = 2048; ldc = 2048; K = 1024;
        } else {
            const int t = x - 136;
            const int z = t >> 8, r = t & 255;
            K = 128; lda = 256; ldb = 256; ldc = 2048;
            if (z < 8) { A = g_qc + z * QH;       B = g_kc + z * QH;       Ch = g_Scls + z * SH; }
            else       { A = g_qr + (z - 8) * QH; B = g_kr + (z - 8) * QH; Ch = g_Sreg + (z - 8) * SH; }
            i0 = (r >> 4) * 128;  j0 = (r & 15) * 128;
        }
    } else {  // MODE 1: PV, fp16 single segment, direct output
        const int head = blockIdx.x >> 5, yt = blockIdx.x & 31;
        K = 2048;
        A = (const bf16*)(g_P  + (size_t)head * NTOK * 2048);
        B = (const bf16*)(g_Vt + (size_t)head * 128  * 2048);
        C = xout + head * 128;
        lda = 2048; ldb = 2048; ldc = 2048;
        i0 = yt * 64; j0 = 0;
    }

    const int nkc = K >> 6;
    const int NC  = (MODE == 1) ? nkc : ((MODE == 3 && symm) ? nkc : 3 * nkc);
    const int tid = threadIdx.x;
    const uint32_t stage0 = (s2u(dsm) + 1023u) & ~1023u;

    const int lane = tid & 31, wid = tid >> 5;
    const int wm = wid % MW, wn = wid / MW;
    const int lt = lane >> 3, lr = lane & 7;
    const int arow = wm * 64 + (lt & 1) * 8 + lr;
    const int brow = wn * (NT * 8) + (lt & 1) * 8 + lr;
    const int kbsub = (lt >> 1) * 16;
    const uint32_t xm = (uint32_t)(lr << 4);

    float acc[4][NT][4];
#pragma unroll
    for (int i = 0; i < 4; i++)
#pragma unroll
        for (int j = 0; j < NT; j++)
#pragma unroll
            for (int q = 0; q < 4; q++) acc[i][j][q] = 0.0f;

    auto fill = [&](int s, int c) {
        const bf16 *Ab, *Bb;
        if (MODE == 1) {
            const int kk = c << 6;
            Ab = A + kk;  Bb = B + kk;
        } else if (MODE == 3 && symm) {
            const int kk = c << 6;
            Ab = A + kk;  Bb = B + kk;
        } else {
            const int seg = c / nkc, kk = (c - seg * nkc) << 6;
            Ab = A + ((seg == 1) ? K : 0) + kk;
            Bb = B + ((seg == 2) ? K : 0) + kk;
        }
        const uint32_t sA = stage0 + (uint32_t)s * STGB, sB = sA + ABYTES;
#pragma unroll
        for (int i = 0; i < 2 * MW; i++) {
            const int id = (i << 8) + tid;
            const int row = id >> 3, c16 = id & 7;
            const uint32_t so = SWZ((uint32_t)((row << 7) + (c16 << 4)));
            cpasync16(sA + so, Ab + (size_t)(i0 + row) * lda + (c16 << 3));
        }
#pragma unroll
        for (int i = 0; i < 4; i++) {
            const int id = (i << 8) + tid;
            const int row = id >> 3, c16 = id & 7;
            const uint32_t so = SWZ((uint32_t)((row << 7) + (c16 << 4)));
            cpasync16(sB + so, Bb + (size_t)(j0 + row) * ldb + (c16 << 3));
        }
    };

#pragma unroll
    for (int c = 0; c < STAGES; c++) { fill(c, c); CP_COMMIT(); }

    for (int c = 0; c < NC; ++c) {
        const int s = c - (c / STAGES) * STAGES;
        CP_WAIT(1);
        __syncthreads();
        if (c >= 1) {
            const int cn = c + 2;
            if (cn < NC) fill(cn - (cn / STAGES) * STAGES, cn);
            CP_COMMIT();
        }
        const uint32_t sA = stage0 + (uint32_t)s * STGB, sB = sA + ABYTES;
#pragma unroll
        for (int ks = 0; ks < 4; ks++) {
            const uint32_t koff = ((uint32_t)(ks * 32 + kbsub)) ^ xm;
            uint32_t a[4][4], b[NP][4];
#pragma unroll
            for (int mt = 0; mt < 4; mt++)
                ldsm4(a[mt][0], a[mt][1], a[mt][2], a[mt][3],
                      sA + (uint32_t)((arow + mt * 16) << 7) + koff);
#pragma unroll
            for (int np = 0; np < NP; np++)
                ldsm4(b[np][0], b[np][1], b[np][2], b[np][3],
                      sB + (uint32_t)((brow + np * 16) << 7) + koff);
#pragma unroll
            for (int mt = 0; mt < 4; mt++)
#pragma unroll
                for (int nt = 0; nt < NT; nt++) {
                    if (MODE == 1)
                        mma16816h(acc[mt][nt], a[mt], b[nt >> 1][nt & 1], b[nt >> 1][(nt & 1) + 2]);
                    else
                        mma16816(acc[mt][nt], a[mt], b[nt >> 1][nt & 1], b[nt >> 1][(nt & 1) + 2]);
                }
        }
    }

    const int rq = lane >> 2, cq = (lane & 3) * 2;
    if (MODE == 3) {
        if (symm) {
#pragma unroll
            for (int mt = 0; mt < 4; mt++) {
                const int row = i0 + wm * 64 + mt * 16 + rq;
#pragma unroll
                for (int nt = 0; nt < NT; nt++) {
                    const int col = j0 + wn * (NT * 8) + nt * 8 + cq;
                    *(__nv_bfloat162*)(g_Svv + (size_t)row * 2048 + col) =
                        __nv_bfloat162(__float2bfloat16(acc[mt][nt][0]), __float2bfloat16(acc[mt][nt][1]));
                    *(__nv_bfloat162*)(g_Svv + (size_t)(row + 8) * 2048 + col) =
                        __nv_bfloat162(__float2bfloat16(acc[mt][nt][2]), __float2bfloat16(acc[mt][nt][3]));
                }
            }
            if (bi != bj) {
                float* smf = (float*)dsm;
                __syncthreads();
#pragma unroll
                for (int mt = 0; mt < 4; mt++) {
                    const int r = wm * 64 + mt * 16 + rq;
#pragma unroll
                    for (int nt = 0; nt < NT; nt++) {
                        const int cc = wn * (NT * 8) + nt * 8 + cq;
                        smf[r * 133 + cc]           = acc[mt][nt][0];
                        smf[r * 133 + cc + 1]       = acc[mt][nt][1];
                        smf[(r + 8) * 133 + cc]     = acc[mt][nt][2];
                        smf[(r + 8) * 133 + cc + 1] = acc[mt][nt][3];
                    }
                }
                __syncthreads();
                const int r2 = tid & 127;
                const int c2b = (tid >> 7) * 64;
                bf16* Crow = g_Svv + (size_t)(j0 + r2) * 2048 + i0 + c2b;
#pragma unroll
                for (int q = 0; q < 16; q++) {
                    union { __nv_bfloat162 h2[2]; uint2 u; } p;
                    p.h2[0] = __nv_bfloat162(__float2bfloat16(smf[(c2b + 4 * q + 0) * 133 + r2]),
                                             __float2bfloat16(smf[(c2b + 4 * q + 1) * 133 + r2]));
                    p.h2[1] = __nv_bfloat162(__float2bfloat16(smf[(c2b + 4 * q + 2) * 133 + r2]),
                                             __float2bfloat16(smf[(c2b + 4 * q + 3) * 133 + r2]));
                    *(uint2*)(Crow + 4 * q) = p.u;
                }
            }
        } else {
#pragma unroll
            for (int mt = 0; mt < 4; mt++) {
                const int row = i0 + wm * 64 + mt * 16 + rq;
#pragma unroll
                for (int nt = 0; nt < NT; nt++) {
                    const int col = j0 + wn * (NT * 8) + nt * 8 + cq;
                    *(__half2*)(Ch + (size_t)row * ldc + col) =
                        __floats2half2_rn(acc[mt][nt][0], acc[mt][nt][1]);
                    *(__half2*)(Ch + (size_t)(row + 8) * ldc + col) =
                        __floats2half2_rn(acc[mt][nt][2], acc[mt][nt][3]);
                }
            }
        }
    } else {
#pragma unroll
        for (int mt = 0; mt < 4; mt++) {
            const int row = i0 + wm * 64 + mt * 16 + rq;
#pragma unroll
            for (int nt = 0; nt < NT; nt++) {
                const int col = j0 + wn * (NT * 8) + nt * 8 + cq;
                const float2 v0 = make_float2(acc[mt][nt][0], acc[mt][nt][1]);
                const float2 v1 = make_float2(acc[mt][nt][2], acc[mt][nt][3]);
                *(float2*)(C + (size_t)row * ldc + col)       = v0;
                *(float2*)(C + (size_t)(row + 8) * ldc + col) = v1;
                if (MODE == 2 && vcols) {
                    *(float2*)(xout + (size_t)row * 2048 + col - 1024)       = v0;
                    *(float2*)(xout + (size_t)(row + 8) * 2048 + col - 1024) = v1;
                }
            }
        }
    }
}

// ---------------- fp32 -> bf16 hi|lo split, float4-vectorized ----------------
__global__ __launch_bounds__(256) void split_x(const float* __restrict__ xc, const float* __restrict__ xr)
{
    const size_t i = ((size_t)blockIdx.x * 256 + threadIdx.x) * 4;
    const int n = (int)(i >> 10), c = (int)(i & 1023);
    const float4 v = *(const float4*)((blockIdx.z == 0 ? xc : xr) + i);
    bf16* o = (blockIdx.z == 0 ? g_Xc : g_Xr) + (size_t)n * 2048 + c;
    const float a[4] = { v.x, v.y, v.z, v.w };
    union { __nv_bfloat162 h2[2]; uint2 u; } ph, pl;
#pragma unroll
    for (int j = 0; j < 2; j++) {
        const bf16 h0 = __float2bfloat16(a[2 * j]);
        const bf16 h1 = __float2bfloat16(a[2 * j + 1]);
        ph.h2[j] = __nv_bfloat162(h0, h1);
        pl.h2[j] = __nv_bfloat162(
            __float2bfloat16(a[2 * j]     - __bfloat162float(h0)),
            __float2bfloat16(a[2 * j + 1] - __bfloat162float(h1)));
    }
    *(uint2*)(o)        = ph.u;
    *(uint2*)(o + 1024) = pl.u;
}

// ---------------- transpose+split body (bf16 hi|lo) ----------------
__device__ __forceinline__ void tsplit_body(
    const float* __restrict__ in, bf16* __restrict__ out,
    int R, int ldin, int ldout, int r0, int c0)
{
    __shared__ float t[32][33];
    const int tx = threadIdx.x & 31, ty = threadIdx.x >> 5;
#pragma unroll
    for (int i = 0; i < 4; i++)
        t[ty + i * 8][tx] = in[(size_t)(r0 + ty + i * 8) * ldin + c0 + tx];
    __syncthreads();
#pragma unroll
    for (int i = 0; i < 4; i++) {
        const int cc = ty + i * 8;
        const float v = t[tx][cc];
        const bf16 h = __float2bfloat16(v);
        out[(size_t)(c0 + cc) * ldout + r0 + tx]     = h;
        out[(size_t)(c0 + cc) * ldout + R + r0 + tx] = __float2bfloat16(v - __bfloat162float(h));
    }
}

// transpose to fp16, single copy (for Vt)
__device__ __forceinline__ void th_body(
    const float* __restrict__ in, __half* __restrict__ out,
    int ldin, int ldout, int r0, int c0)
{
    __shared__ float t[32][33];
    const int tx = threadIdx.x & 31, ty = threadIdx.x >> 5;
#pragma unroll
    for (int i = 0; i < 4; i++)
        t[ty + i * 8][tx] = in[(size_t)(r0 + ty + i * 8) * ldin + c0 + tx];
    __syncthreads();
#pragma unroll
    for (int i = 0; i < 4; i++) {
        const int cc = ty + i * 8;
        out[(size_t)(c0 + cc) * ldout + r0 + tx] = __float2half_rn(t[tx][cc]);
    }
}

__global__ __launch_bounds__(256) void w_prep(
    const float* __restrict__ Wcls, const float* __restrict__ Wreg)
{
    const int x = blockIdx.x;
    if (x < 3072) {
        tsplit_body(Wcls, g_Wc, 1024, 3072, 2048, (x / 96) * 32, (x % 96) * 32);
    } else {
        const int t2 = x - 3072;
        tsplit_body(Wreg, g_Wr, 1024, 3072, 2048, (t2 / 64) * 32, (t2 % 64) * 32);
    }
}

// ---------------- merged: L2-normalize+split (x<10240) OR Vt fp16 transpose ----------
__global__ __launch_bounds__(256) void norm_vt()
{
    if (blockIdx.x < 10240) {
        const int gid  = blockIdx.x * 8 + (threadIdx.x >> 5);
        const int lane = threadIdx.x & 31;
        const int op  = gid / (NTOK * HEADS);
        const int rem = gid - op * (NTOK * HEADS);
        const int n = rem >> 3, h = rem & 7;

        const float* src; bf16* dst; int lo_off;
        if (op == 0)      { src = g_qkv_cls + (size_t)n * 3072 + h * 128;        dst = g_qc + ((size_t)h * NTOK + n) * 256; lo_off = 128; }
        else if (op == 1) { src = g_qkv_cls + (size_t)n * 3072 + 1024 + h * 128; dst = g_kc + ((size_t)h * NTOK + n) * 256; lo_off = 128; }
        else if (op == 2) { src = g_qk_reg  + (size_t)n * 2048 + h * 128;        dst = g_qr + ((size_t)h * NTOK + n) * 256; lo_off = 128; }
        else if (op == 3) { src = g_qk_reg  + (size_t)n * 2048 + 1024 + h * 128; dst = g_kr + ((size_t)h * NTOK + n) * 256; lo_off = 128; }
        else              { src = g_qkv_cls + (size_t)n * 3072 + 2048 + h * 128; dst = g_vn + (size_t)n * 2048 + h * 128;   lo_off = 0; }

        float4 v = *(const float4*)(src + lane * 4);
        float ss = v.x * v.x + v.y * v.y + v.z * v.z + v.w * v.w;
#pragma unroll
        for (int o = 16; o; o >>= 1) ss += __shfl_xor_sync(0xffffffffu, ss, o);
        const float r = 1.0f / sqrtf(ss);
        float a[4] = { v.x * r, v.y * r, v.z * r, v.w * r };
#pragma unroll
        for (int j = 0; j < 4; j++) {
            const bf16 h2 = __float2bfloat16(a[j]);
            dst[lane * 4 + j] = h2;
            if (lo_off)
                dst[lo_off + lane * 4 + j] = __float2bfloat16(a[j] - __bfloat162float(h2));
        }
    } else {
        const int t2 = (int)blockIdx.x - 10240;        // 0..2047
        const int bz = t2 >> 8, rem = t2 & 255;
        const int by = rem >> 2, bx = rem & 3;
        th_body(g_qkv_cls + 2048 + bz * 128, g_Vt + (size_t)bz * 128 * 2048,
                3072, 2048, by * 32, bx * 32);
    }
}

// ---------------- FMA-only exp + block reductions ----------------
__device__ __forceinline__ float fast_exp(float x)
{
    float t = x * 1.4426950408889634f;
    t = fmaxf(t, -120.0f);
    float r = t + 12582912.0f;
    float f = t - (r - 12582912.0f);
    int   k = __float_as_int(r) - 0x4B400000;
    float p = 1.5403530393381609e-4f;
    p = fmaf(p, f, 1.3333558146428443e-3f);
    p = fmaf(p, f, 9.618129107628477e-3f);
    p = fmaf(p, f, 5.550410866482158e-2f);
    p = fmaf(p, f, 2.402265069591007e-1f);
    p = fmaf(p, f, 6.931471805599453e-1f);
    p = fmaf(p, f, 1.0f);
    return p * __int_as_float((k + 127) << 23);
}
__device__ __forceinline__ float block_max(float v, float* red)
{
#pragma unroll
    for (int o = 16; o; o >>= 1) v = fmaxf(v, __shfl_xor_sync(0xffffffffu, v, o));
    if ((threadIdx.x & 31) == 0) red[threadIdx.x >> 5] = v;
    __syncthreads();
    float r = red[0];
#pragma unroll
    for (int i = 1; i < 8; i++) r = fmaxf(r, red[i]);
    __syncthreads();
    return r;
}
__device__ __forceinline__ float block_sum(float v, float* red)
{
#pragma unroll
    for (int o = 16; o; o >>= 1) v += __shfl_xor_sync(0xffffffffu, v, o);
    if ((threadIdx.x & 31) == 0) red[threadIdx.x >> 5] = v;
    __syncthreads();
    float r = red[0];
#pragma unroll
    for (int i = 1; i < 8; i++) r += red[i];
    __syncthreads();
    return r;
}
__device__ __forceinline__ void block_sum2(float& a, float& b, float* red2)
{
#pragma unroll
    for (int o = 16; o; o >>= 1) {
        a += __shfl_xor_sync(0xffffffffu, a, o);
        b += __shfl_xor_sync(0xffffffffu, b, o);
    }
    if ((threadIdx.x & 31) == 0) {
        red2[(threadIdx.x >> 5) * 2]     = a;
        red2[(threadIdx.x >> 5) * 2 + 1] = b;
    }
    __syncthreads();
    float ra = red2[0], rb = red2[1];
#pragma unroll
    for (int i = 1; i < 8; i++) { ra += red2[i * 2]; rb += red2[i * 2 + 1]; }
    __syncthreads();
    a = ra; b = rb;
}

// ---------------- fused masked dual softmax + combine + sim_round2 -----------------
__global__ __launch_bounds__(256) void row_fuse(
    const float* __restrict__ cls_score, const float* __restrict__ fg_score,
    float* __restrict__ out_sim)
{
    const int n = blockIdx.x;
    const int tid = threadIdx.x;
    const int m0 = tid * 8;
    __shared__ float s_sc[NTOK];
    __shared__ float red[16];

    float fc[8], fr[8];
    float lsc = -1e30f, lfs = -1e30f;
#pragma unroll
    for (int j = 0; j < 8; j++) {
        const int m = m0 + j;
        const float a = cls_score[m], b = fg_score[m];
        fc[j] = a;  fr[j] = b;
        s_sc[m] = a;
        lsc = fmaxf(lsc, a);  lfs = fmaxf(lfs, b);
    }
    __syncthreads();
    const float Mc = 25.0f * block_max(lsc, red) + 1.0f;
    const float Mr = 25.0f * block_max(lfs, red) + 1.0f;
    const float cthr = s_sc[n] - 0.1f;
    const float fthr = fg_score[n] - 0.1f;
#pragma unroll
    for (int j = 0; j < 8; j++) {
        fc[j] = (fc[j] > cthr) ? 25.0f * fc[j] : 0.0f;
        fr[j] = (fr[j] > fthr) ? 25.0f * fr[j] : 0.0f;
    }

    float vvacc[8];
    {
        const uint4 u = *(const uint4*)(g_Svv + (size_t)n * NTOK + m0);
        const __nv_bfloat162* hv = (const __nv_bfloat162*)&u;
#pragma unroll
        for (int j = 0; j < 4; j++) {
            vvacc[2 * j]     = __bfloat162float(hv[j].x);
            vvacc[2 * j + 1] = __bfloat162float(hv[j].y);
        }
    }

    float simacc[8];
#pragma unroll
    for (int j = 0; j < 8; j++) simacc[j] = 0.0f;

    for (int h = 0; h < HEADS; h++) {
        const size_t base = ((size_t)h * NTOK + n) * NTOK + m0;
        __half* Pb = g_P + ((size_t)h * NTOK + n) * 2048 + m0;
        float ec[8], er[8], sv[8];

        {
            const uint4 u = *(const uint4*)(g_Scls + base);
            const __half2* hp = (const __half2*)&u;
#pragma unroll
            for (int j = 0; j < 4; j++) {
                const float2 f = __half22float2(hp[j]);
                sv[2 * j] = f.x;  sv[2 * j + 1] = f.y;
            }
        }
        float smc = 0.0f;
#pragma unroll
        for (int j = 0; j < 8; j++) { ec[j] = fast_exp(sv[j] * fc[j] - Mc); smc += ec[j]; }

        {
            const uint4 u = *(const uint4*)(g_Sreg + base);
            const __half2* hp = (const __half2*)&u;
#pragma unroll
            for (int j = 0; j < 4; j++) {
                const float2 f = __half22float2(hp[j]);
                sv[2 * j] = f.x;  sv[2 * j + 1] = f.y;
            }
        }
        float smr = 0.0f;
#pragma unroll
        for (int j = 0; j < 8; j++) { er[j] = fast_exp(sv[j] * fr[j] - Mr); smr += er[j]; }

        block_sum2(smc, smr, red);
        const float ic = 0.5f / smc, ir = 0.5f / smr;

        float pv[8];
#pragma unroll
        for (int j = 0; j < 8; j++) pv[j] = ec[j] * ic + er[j] * ir;

        union { __half2 h2[4]; uint4 u; } ph;
#pragma unroll
        for (int j = 0; j < 4; j++)
            ph.h2[j] = __floats2half2_rn(pv[2 * j], pv[2 * j + 1]);
        *(uint4*)(Pb) = ph.u;

#pragma unroll
        for (int j = 0; j < 8; j++) simacc[j] += pv[j];
    }

    float sm = 0.0f;
#pragma unroll
    for (int j = 0; j < 8; j++) { simacc[j] = fast_exp(simacc[j] * 0.125f - 1.0f); sm += simacc[j]; }
    sm = block_sum(sm, red);
    float msum = 0.0f;
#pragma unroll
    for (int j = 0; j < 8; j++) {
        const float soft = simacc[j] / sm;
        const float keep = (vvacc[j] > 6.0f) ? soft : 0.0f;
        simacc[j] = keep; msum += keep;
    }
    msum = block_sum(msum, red);
    const float rn = 1.0f / msum;
    float4 o0 = make_float4(simacc[0] * rn, simacc[1] * rn, simacc[2] * rn, simacc[3] * rn);
    float4 o1 = make_float4(simacc[4] * rn, simacc[5] * rn, simacc[6] * rn, simacc[7] * rn);
    *(float4*)(out_sim + (size_t)n * NTOK + m0)     = o0;
    *(float4*)(out_sim + (size_t)n * NTOK + m0 + 4) = o1;
}

// -------------------------------- launch ----------------------------------------
extern "C" void kernel_launch(void* const* d_in, const int* in_sizes, int n_in,
                              void* d_out, int out_size)
{
    (void)in_sizes; (void)n_in; (void)out_size;
    const float* x_cls     = (const float*)d_in[0];
    const float* x_reg     = (const float*)d_in[1];
    const float* cls_score = (const float*)d_in[2];
    const float* fg_score  = (const float*)d_in[3];
    const float* W_cls     = (const float*)d_in[4];
    const float* W_reg     = (const float*)d_in[5];
    float* out = (float*)d_out;

    const int DS1 = STAGES * 24576 + 1024;   // MW=1 stages (64x128), 3 CTAs/SM
    const int DS2 = STAGES * 32768 + 1024;   // MW=2 stages (128x128), 2 CTAs/SM
    cudaFuncSetAttribute((const void*)hm_gemm_k<1>, cudaFuncAttributeMaxDynamicSharedMemorySize, DS1);
    cudaFuncSetAttribute((const void*)hm_gemm_k<2>, cudaFuncAttributeMaxDynamicSharedMemorySize, DS1);
    cudaFuncSetAttribute((const void*)hm_gemm_k<3>, cudaFuncAttributeMaxDynamicSharedMemorySize, DS2);

    // 1) split inputs (vectorized); merged W transpose/split
    split_x<<<dim3(2048, 1, 2), 256>>>(x_cls, x_reg);
    w_prep<<<3072 + 2048, 256>>>(W_cls, W_reg);

    // 2) qkv projections (cls v-columns also write x_ori -> out[:,1024:2048])
    hm_gemm_k<2><<<1280, 256, DS1>>>(out);

    // 3) normalize q/k/v + Vt fp16 transpose, merged into one launch
    norm_vt<<<10240 + 2048, 256>>>();

    // 4) scores (fp16 out, 16 planes) + single-segment symmetric vv (bf16 out)
    hm_gemm_k<3><<<4232, 256, DS2>>>(nullptr);

    // 5) fused softmax + sim (reads fp16 S*, writes fp16 P + sim output)
    row_fuse<<<NTOK, 256>>>(cls_score, fg_score, out + (size_t)NTOK * NTOK);

    // 6) x = P @ V, fp16 single-segment, ONE wave, writes out[:,0:1024] directly
    hm_gemm_k<1><<<256, 256, DS1>>>(out);
}